// round 7
// baseline (speedup 1.0000x reference)
#include <cuda_runtime.h>
#include <cstdint>
#include <math.h>

// ---------------- scratch (static __device__, no allocation) ----------------
__device__ float g_part[4*4*3*4096];     // attention partials [b][ks][3][q]
__device__ float g_warp[4*2*4096];       // coarse_warp [b][2][p]
__device__ float g_cat[3670016];         // concat input: coarse 4*136*4096 / fine 4*56*16384
__device__ float g_bufA[4194304];        // conv out (pre-BN)
__device__ float g_bufB[4194304];        // BN+ReLU out (only needed before heads)
__device__ float g_up[4*3*16384];        // upsampled coarse matches
__device__ float g_mean[256];
__device__ float g_istd[256];

// ---------------- fused correlation-softmax-expectation ----------------
__global__ void __launch_bounds__(256) attn_kernel(const float* __restrict__ f0,
                                                   const float* __restrict__ f1)
{
    __shared__ __align__(16) float sK[64][64];
    const int qb = blockIdx.x, ks = blockIdx.y, b = blockIdx.z;
    const int q = qb*256 + threadIdx.x;
    const float* f0b = f0 + (size_t)b*262144;
    const float* f1b = f1 + (size_t)b*262144;
    float qv[64];
#pragma unroll
    for (int c=0;c<64;c++) qv[c] = f0b[c*4096 + q];
    float sE=0.f, sX=0.f, sY=0.f;
    const int kbase = ks*1024;
    for (int t=0; t<1024; t+=64) {
        __syncthreads();
        const int k0 = kbase + t;
        for (int idx=threadIdx.x; idx<4096; idx+=256) {
            int c = idx>>6, kk = idx&63;
            sK[c][kk] = f1b[c*4096 + k0 + kk];
        }
        __syncthreads();
        const float gyv = (float)((k0>>6)*2 + 1)*0.015625f - 1.0f;
        for (int kk=0; kk<64; kk+=4) {
            float d0=0.f,d1=0.f,d2=0.f,d3=0.f;
#pragma unroll
            for (int c=0;c<64;c++) {
                float4 kv = *(const float4*)&sK[c][kk];
                d0 = fmaf(qv[c], kv.x, d0);
                d1 = fmaf(qv[c], kv.y, d1);
                d2 = fmaf(qv[c], kv.z, d2);
                d3 = fmaf(qv[c], kv.w, d3);
            }
            float e0 = __expf(d0*0.125f);
            float e1 = __expf(d1*0.125f);
            float e2 = __expf(d2*0.125f);
            float e3 = __expf(d3*0.125f);
            float gx0 = (float)((((k0+kk)&63)*2)+1)*0.015625f - 1.0f;
            float es = e0+e1+e2+e3;
            sE += es;
            sY = fmaf(es, gyv, sY);
            sX += e0*gx0 + e1*(gx0+0.03125f) + e2*(gx0+0.0625f) + e3*(gx0+0.09375f);
        }
    }
    size_t base = ((size_t)(b*4+ks)*3)*4096 + q;
    g_part[base        ] = sE;
    g_part[base +  4096] = sX;
    g_part[base +  8192] = sY;
}

__global__ void attn_combine()
{
    int i = blockIdx.x*256 + threadIdx.x;      // 16384
    if (i >= 16384) return;
    int b = i>>12, q = i&4095;
    float sE=0.f, sX=0.f, sY=0.f;
    for (int ks=0; ks<4; ks++) {
        size_t base = ((size_t)(b*4+ks)*3)*4096 + q;
        sE += g_part[base];
        sX += g_part[base+4096];
        sY += g_part[base+8192];
    }
    float inv = 1.0f/sE;
    g_warp[(size_t)(b*2  )*4096 + q] = sX*inv;
    g_warp[(size_t)(b*2+1)*4096 + q] = sY*inv;
}

// ---------------- coarse concat + grid_sample (zero padding) ----------------
__global__ void pack_coarse(const float* __restrict__ f0c, const float* __restrict__ f1c)
{
    int i = blockIdx.x*256 + threadIdx.x;      // 16384
    if (i >= 16384) return;
    int b = i>>12, p = i&4095;
    float wx = g_warp[(size_t)(b*2  )*4096 + p];
    float wy = g_warp[(size_t)(b*2+1)*4096 + p];
    float* xb = g_cat + (size_t)b*136*4096;
    if (blockIdx.y == 0) {
        xb[(size_t)128*4096 + p] = wx;
        xb[(size_t)129*4096 + p] = wy;
#pragma unroll
        for (int c=130;c<136;c++) xb[(size_t)c*4096 + p] = 0.f;
    }

    float fx = (wx + 1.f)*32.f - 0.5f;
    float fy = (wy + 1.f)*32.f - 0.5f;
    float flx = floorf(fx), fly = floorf(fy);
    float ax = fx - flx, ay = fy - fly;
    int xi = (int)flx, yi = (int)fly;
    float vx0 = ((unsigned)xi     < 64u) ? 1.f : 0.f;
    float vx1 = ((unsigned)(xi+1) < 64u) ? 1.f : 0.f;
    float vy0 = ((unsigned)yi     < 64u) ? 1.f : 0.f;
    float vy1 = ((unsigned)(yi+1) < 64u) ? 1.f : 0.f;
    int cx0 = min(max(xi,0),63),   cx1 = min(max(xi+1,0),63);
    int cy0 = min(max(yi,0),63),   cy1 = min(max(yi+1,0),63);
    float w00 = (1.f-ax)*(1.f-ay)*vx0*vy0;
    float w01 = ax*(1.f-ay)*vx1*vy0;
    float w10 = (1.f-ax)*ay*vx0*vy1;
    float w11 = ax*ay*vx1*vy1;
    const float* f1b = f1c + (size_t)b*262144;
    const float* f0b = f0c + (size_t)b*262144;
    int i00 = cy0*64+cx0, i01 = cy0*64+cx1, i10 = cy1*64+cx0, i11 = cy1*64+cx1;
    int cs = blockIdx.y*16;
    for (int c=cs;c<cs+16;c++) {
        const float* fc = f1b + (size_t)c*4096;
        float v = w00*fc[i00] + w01*fc[i01] + w10*fc[i10] + w11*fc[i11];
        xb[(size_t)(64+c)*4096 + p] = v;
        xb[(size_t)c*4096 + p]      = f0b[(size_t)c*4096 + p];
    }
}

// ---------------- direct 3x3 conv, SAME pad, no bias ----------------
// Block: 16 oc x (two sequential 8x32 tiles). 256 thr, each 4 oc x 4 px.
// Warp = 4 rows x 8 x-groups -> with odd sIn row stride (35), scalar LDS is
// provably conflict-free (Δgy in {1,2,3}: 3*Δgy mod 4 != 0 = Δgx mod 4).
// Optional fused input BN+ReLU (bnm/bni per-channel; nullptr = raw input).
template<int CINP>
__global__ void __launch_bounds__(256) conv3x3_kernel(
    const float* __restrict__ in, const float* __restrict__ wgt,
    float* __restrict__ out,
    const float* __restrict__ bnm, const float* __restrict__ bni,
    int cinReal, int cout, int H, int W)
{
    __shared__ __align__(16) float sIn[8][10][35];
    __shared__ __align__(16) float sW[8][9][16];
    const int HW = H*W;
    const int tilesX = W >> 5;
    const int px = blockIdx.x % tilesX;
    const int pyPair = blockIdx.x / tilesX;
    const int ocb = blockIdx.y << 4;
    const int b = blockIdx.z;
    const int tid = threadIdx.x;
    const int lane = tid & 31;
    const int wid = tid >> 5;
    const int ocg = wid & 3;
    const int slab = wid >> 2;
    const int gy = (slab << 2) + (lane >> 3);   // row 0..7
    const int gx = (lane & 7) << 2;             // x base: 0,4,...,28
    const int ocl = ocg << 2;                   // local oc base 0,4,8,12
    const int x0 = px << 5;
    const float* inB = in + (size_t)b*CINP*HW;
    const bool doBN = (bnm != nullptr);

    for (int t = 0; t < 2; t++) {
        const int y0 = ((pyPair<<1) + t) << 3;

        float acc[4][4];
#pragma unroll
        for (int o=0;o<4;o++)
#pragma unroll
            for (int j=0;j<4;j++) acc[o][j] = 0.f;

        for (int c0=0; c0<CINP; c0+=8) {
            __syncthreads();
            // input halo tile 10 x 34 x 8ic (with optional fused BN+ReLU)
            for (int idx=tid; idx<2720; idx+=256) {
                int ic = idx/340;
                int rem = idx - ic*340;
                int r  = rem/34;
                int cl = rem - r*34;
                int yy = y0-1+r, xx = x0-1+cl;
                float v = 0.f;
                if ((unsigned)yy < (unsigned)H && (unsigned)xx < (unsigned)W) {
                    v = inB[(size_t)(c0+ic)*HW + yy*W + xx];
                    if (doBN)
                        v = fmaxf((v - bnm[c0+ic])*bni[c0+ic], 0.f);
                }
                sIn[ic][r][cl] = v;
            }
            // weights [ic][k][16oc], zero for padded ic
            for (int idx=tid; idx<1152; idx+=256) {
                int ic = idx/144;
                int rem = idx - ic*144;
                int k  = rem >> 4;
                int o  = rem & 15;
                int icg = c0 + ic;
                float v = 0.f;
                if (icg < cinReal)
                    v = wgt[((size_t)(ocb+o)*cinReal + icg)*9 + k];
                sW[ic][k][o] = v;
            }
            __syncthreads();
#pragma unroll
            for (int ic=0;ic<8;ic++) {
#pragma unroll
                for (int kh=0;kh<3;kh++) {
                    float r[6];
#pragma unroll
                    for (int j=0;j<6;j++) r[j] = sIn[ic][gy+kh][gx+j];
#pragma unroll
                    for (int kw=0;kw<3;kw++) {
                        float4 w4 = *(const float4*)&sW[ic][kh*3+kw][ocl];
#pragma unroll
                        for (int j=0;j<4;j++) {
                            acc[0][j] = fmaf(w4.x, r[j+kw], acc[0][j]);
                            acc[1][j] = fmaf(w4.y, r[j+kw], acc[1][j]);
                            acc[2][j] = fmaf(w4.z, r[j+kw], acc[2][j]);
                            acc[3][j] = fmaf(w4.w, r[j+kw], acc[3][j]);
                        }
                    }
                }
            }
        }
#pragma unroll
        for (int o=0;o<4;o++) {
            float4 v = make_float4(acc[o][0], acc[o][1], acc[o][2], acc[o][3]);
            *(float4*)&out[((size_t)b*cout + (ocb+ocl+o))*HW + (y0+gy)*W + x0+gx] = v;
        }
    }
}

// ---------------- batch-norm: per-channel stats over (B,H,W) ----------------
__global__ void bn_reduce(const float* __restrict__ x, int C, int HW)
{
    const int c = blockIdx.x;
    const int tid = threadIdx.x;
    float s = 0.f, s2 = 0.f;
    for (int b=0;b<4;b++) {
        const float* xb = x + ((size_t)b*C + c)*HW;
        for (int p=tid; p<HW; p+=256) {
            float v = xb[p];
            s += v; s2 += v*v;
        }
    }
    __shared__ float rs[256];
    __shared__ float rq[256];
    rs[tid] = s; rq[tid] = s2;
    __syncthreads();
    for (int off=128; off>0; off>>=1) {
        if (tid < off) { rs[tid]+=rs[tid+off]; rq[tid]+=rq[tid+off]; }
        __syncthreads();
    }
    if (tid == 0) {
        float invN = 1.0f/(4.0f*HW);
        float m = rs[0]*invN;
        float var = rq[0]*invN - m*m;
        g_mean[c] = m;
        g_istd[c] = rsqrtf(var + 1e-5f);
    }
}

__global__ void bn_apply(const float* __restrict__ x, float* __restrict__ y,
                         int cMask, int hwShift)
{
    int idx = blockIdx.x*256 + threadIdx.x;
    int c = (idx >> hwShift) & cMask;
    float v = (x[idx] - g_mean[c]) * g_istd[c];
    y[idx] = fmaxf(v, 0.f);
}

// ---------------- heads (1x1 conv + bias + residual) ----------------
__global__ void head_coarse(const float* __restrict__ w, const float* __restrict__ bias,
                            float* __restrict__ out)
{
    __shared__ float sw[768];
    for (int idx=threadIdx.x; idx<768; idx+=256) sw[idx] = w[idx];
    __syncthreads();
    int i = blockIdx.x*256 + threadIdx.x;     // 16384
    int b = i>>12, p = i&4095;
    const float* xb = g_bufB + (size_t)b*256*4096 + p;
    float a0 = bias[0], a1 = bias[1], a2 = bias[2];
    for (int c=0;c<256;c++) {
        float v = xb[(size_t)c*4096];
        a0 = fmaf(v, sw[c],     a0);
        a1 = fmaf(v, sw[256+c], a1);
        a2 = fmaf(v, sw[512+c], a2);
    }
    out[(size_t)(b*3  )*4096 + p] = g_warp[(size_t)(b*2  )*4096 + p] + a0;
    out[(size_t)(b*3+1)*4096 + p] = g_warp[(size_t)(b*2+1)*4096 + p] + a1;
    out[(size_t)(b*3+2)*4096 + p] = a2;
}

// ---------------- 2x bilinear upsample (half-pixel, edge-clamped) ----------------
__global__ void upsample_kernel(const float* __restrict__ cm)
{
    int idx = blockIdx.x*256 + threadIdx.x;   // 196608
    if (idx >= 196608) return;
    int p  = idx & 16383;
    int bc = idx >> 14;
    int ox = p & 127, oy = p >> 7;
    float sx = 0.5f*ox - 0.25f;
    float sy = 0.5f*oy - 0.25f;
    float fx = floorf(sx), fy = floorf(sy);
    float ax = sx - fx, ay = sy - fy;
    int x0 = (int)fx, y0 = (int)fy;
    int x0c = max(x0,0), x1c = min(x0+1,63);
    int y0c = max(y0,0), y1c = min(y0+1,63);
    const float* inb = cm + (size_t)bc*4096;
    float v00 = inb[y0c*64+x0c], v01 = inb[y0c*64+x1c];
    float v10 = inb[y1c*64+x0c], v11 = inb[y1c*64+x1c];
    g_up[idx] = (1.f-ay)*((1.f-ax)*v00 + ax*v01) + ay*((1.f-ax)*v10 + ax*v11);
}

// ---------------- fine concat + grid_sample ----------------
__global__ void pack_fine(const float* __restrict__ f0f, const float* __restrict__ f1f)
{
    int i = blockIdx.x*256 + threadIdx.x;     // 65536
    if (i >= 65536) return;
    int b = i>>14, p = i&16383;
    float wx = g_up[(size_t)(b*3  )*16384 + p];
    float wy = g_up[(size_t)(b*3+1)*16384 + p];
    float* yb = g_cat + (size_t)b*56*16384;
    if (blockIdx.y == 0) {
        yb[(size_t)48*16384 + p] = wx;
        yb[(size_t)49*16384 + p] = wy;
#pragma unroll
        for (int c=50;c<56;c++) yb[(size_t)c*16384 + p] = 0.f;
    }

    float fx = (wx + 1.f)*64.f - 0.5f;
    float fy = (wy + 1.f)*64.f - 0.5f;
    float flx = floorf(fx), fly = floorf(fy);
    float ax = fx - flx, ay = fy - fly;
    int xi = (int)flx, yi = (int)fly;
    float vx0 = ((unsigned)xi     < 128u) ? 1.f : 0.f;
    float vx1 = ((unsigned)(xi+1) < 128u) ? 1.f : 0.f;
    float vy0 = ((unsigned)yi     < 128u) ? 1.f : 0.f;
    float vy1 = ((unsigned)(yi+1) < 128u) ? 1.f : 0.f;
    int cx0 = min(max(xi,0),127),  cx1 = min(max(xi+1,0),127);
    int cy0 = min(max(yi,0),127),  cy1 = min(max(yi+1,0),127);
    float w00 = (1.f-ax)*(1.f-ay)*vx0*vy0;
    float w01 = ax*(1.f-ay)*vx1*vy0;
    float w10 = (1.f-ax)*ay*vx0*vy1;
    float w11 = ax*ay*vx1*vy1;
    const float* f1b = f1f + (size_t)b*24*16384;
    const float* f0b = f0f + (size_t)b*24*16384;
    int i00 = cy0*128+cx0, i01 = cy0*128+cx1, i10 = cy1*128+cx0, i11 = cy1*128+cx1;
    int cs = blockIdx.y*6;
    for (int c=cs;c<cs+6;c++) {
        const float* fc = f1b + (size_t)c*16384;
        float v = w00*fc[i00] + w01*fc[i01] + w10*fc[i10] + w11*fc[i11];
        yb[(size_t)(24+c)*16384 + p] = v;
        yb[(size_t)c*16384 + p]      = f0b[(size_t)c*16384 + p];
    }
}

__global__ void head_fine(const float* __restrict__ w, const float* __restrict__ bias,
                          float* __restrict__ out)
{
    __shared__ float sw[192];
    for (int idx=threadIdx.x; idx<192; idx+=256) sw[idx] = w[idx];
    __syncthreads();
    int i = blockIdx.x*256 + threadIdx.x;     // 65536
    int b = i>>14, p = i&16383;
    const float* yb = g_bufB + (size_t)b*64*16384 + p;
    float a0 = bias[0], a1 = bias[1], a2 = bias[2];
    for (int c=0;c<64;c++) {
        float v = yb[(size_t)c*16384];
        a0 = fmaf(v, sw[c],      a0);
        a1 = fmaf(v, sw[64+c],   a1);
        a2 = fmaf(v, sw[128+c],  a2);
    }
    out[(size_t)(b*3  )*16384 + p] = g_up[(size_t)(b*3  )*16384 + p] + a0;
    out[(size_t)(b*3+1)*16384 + p] = g_up[(size_t)(b*3+1)*16384 + p] + a1;
    out[(size_t)(b*3+2)*16384 + p] = g_up[(size_t)(b*3+2)*16384 + p] + a2;
}

// ---------------- launch ----------------
extern "C" void kernel_launch(void* const* d_in, const int* in_sizes, int n_in,
                              void* d_out, int out_size)
{
    const float* f0c = (const float*)d_in[0];
    const float* f1c = (const float*)d_in[1];
    const float* f0f = (const float*)d_in[2];
    const float* f1f = (const float*)d_in[3];
    const float* cw1 = (const float*)d_in[4];
    const float* cw2 = (const float*)d_in[5];
    const float* cw3 = (const float*)d_in[6];
    const float* cw4 = (const float*)d_in[7];
    const float* cw5 = (const float*)d_in[8];
    const float* cb5 = (const float*)d_in[9];
    const float* fw1 = (const float*)d_in[10];
    const float* fw2 = (const float*)d_in[11];
    const float* fw3 = (const float*)d_in[12];
    const float* fw4 = (const float*)d_in[13];
    const float* fw5 = (const float*)d_in[14];
    const float* fb5 = (const float*)d_in[15];

    float *pCat, *pA, *pB, *pM, *pI;
    cudaGetSymbolAddress((void**)&pCat, g_cat);
    cudaGetSymbolAddress((void**)&pA,   g_bufA);
    cudaGetSymbolAddress((void**)&pB,   g_bufB);
    cudaGetSymbolAddress((void**)&pM,   g_mean);
    cudaGetSymbolAddress((void**)&pI,   g_istd);

    float* outC = (float*)d_out;          // (4,3,64,64)
    float* outF = outC + 49152;           // (4,3,128,128)

    // coarse attention -> warp field
    attn_kernel<<<dim3(16,4,4),256>>>(f0c, f1c);
    attn_combine<<<64,256>>>();
    pack_coarse<<<dim3(64,4),256>>>(f0c, f1c);

    // coarse conv tower: conv -> stats; BN+ReLU fused into the NEXT conv's load
    // grid: (tilesX * tilesY/2, cout/16, B) = (8, 16, 4) -> 512 blocks (single wave)
    conv3x3_kernel<136><<<dim3(8,16,4),256>>>(pCat, cw1, pA, nullptr, nullptr, 130, 256, 64, 64);
    bn_reduce<<<256,256>>>(pA, 256, 4096);
    conv3x3_kernel<256><<<dim3(8,16,4),256>>>(pA, cw2, pB, pM, pI, 256, 256, 64, 64);
    bn_reduce<<<256,256>>>(pB, 256, 4096);
    conv3x3_kernel<256><<<dim3(8,16,4),256>>>(pB, cw3, pA, pM, pI, 256, 256, 64, 64);
    bn_reduce<<<256,256>>>(pA, 256, 4096);
    conv3x3_kernel<256><<<dim3(8,16,4),256>>>(pA, cw4, pB, pM, pI, 256, 256, 64, 64);
    bn_reduce<<<256,256>>>(pB, 256, 4096);
    bn_apply<<<16384,256>>>(pB, pB, 255, 12);     // materialize BN for head

    head_coarse<<<64,256>>>(cw5, cb5, outC);

    // fine stage
    upsample_kernel<<<768,256>>>(outC);
    pack_fine<<<dim3(256,4),256>>>(f0f, f1f);

    // fine grid: (4 * 16/2, 64/16, 4) = (32, 4, 4) -> 512 blocks
    conv3x3_kernel<56><<<dim3(32,4,4),256>>>(pCat, fw1, pA, nullptr, nullptr, 50, 64, 128, 128);
    bn_reduce<<<64,256>>>(pA, 64, 16384);
    conv3x3_kernel<64><<<dim3(32,4,4),256>>>(pA, fw2, pB, pM, pI, 64, 64, 128, 128);
    bn_reduce<<<64,256>>>(pB, 64, 16384);
    conv3x3_kernel<64><<<dim3(32,4,4),256>>>(pB, fw3, pA, pM, pI, 64, 64, 128, 128);
    bn_reduce<<<64,256>>>(pA, 64, 16384);
    conv3x3_kernel<64><<<dim3(32,4,4),256>>>(pA, fw4, pB, pM, pI, 64, 64, 128, 128);
    bn_reduce<<<64,256>>>(pB, 64, 16384);
    bn_apply<<<16384,256>>>(pB, pB, 63, 14);      // materialize BN for head

    head_fine<<<256,256>>>(fw5, fb5, outF);
}

// round 8
// speedup vs baseline: 1.0438x; 1.0438x over previous
#include <cuda_runtime.h>
#include <cstdint>
#include <math.h>

// ---------------- scratch (static __device__, no allocation) ----------------
__device__ float g_part[4*4*3*4096];     // attention partials [b][ks][3][q]
__device__ float g_warp[4*2*4096];       // coarse_warp [b][2][p]
__device__ float g_cat[3670016];         // concat input: coarse 4*136*4096 / fine 4*56*16384
__device__ float g_bufA[4194304];        // conv out (pre-BN)
__device__ float g_bufB[4194304];        // BN+ReLU out (only needed before heads)
__device__ float g_up[4*3*16384];        // upsampled coarse matches
__device__ float g_mean[256];
__device__ float g_istd[256];

// ---------------- fused correlation-softmax-expectation ----------------
__global__ void __launch_bounds__(256) attn_kernel(const float* __restrict__ f0,
                                                   const float* __restrict__ f1)
{
    __shared__ __align__(16) float sK[64][64];
    const int qb = blockIdx.x, ks = blockIdx.y, b = blockIdx.z;
    const int q = qb*256 + threadIdx.x;
    const float* f0b = f0 + (size_t)b*262144;
    const float* f1b = f1 + (size_t)b*262144;
    float qv[64];
#pragma unroll
    for (int c=0;c<64;c++) qv[c] = f0b[c*4096 + q];
    float sE=0.f, sX=0.f, sY=0.f;
    const int kbase = ks*1024;
    for (int t=0; t<1024; t+=64) {
        __syncthreads();
        const int k0 = kbase + t;
        for (int idx=threadIdx.x; idx<4096; idx+=256) {
            int c = idx>>6, kk = idx&63;
            sK[c][kk] = f1b[c*4096 + k0 + kk];
        }
        __syncthreads();
        const float gyv = (float)((k0>>6)*2 + 1)*0.015625f - 1.0f;
        for (int kk=0; kk<64; kk+=4) {
            float d0=0.f,d1=0.f,d2=0.f,d3=0.f;
#pragma unroll
            for (int c=0;c<64;c++) {
                float4 kv = *(const float4*)&sK[c][kk];
                d0 = fmaf(qv[c], kv.x, d0);
                d1 = fmaf(qv[c], kv.y, d1);
                d2 = fmaf(qv[c], kv.z, d2);
                d3 = fmaf(qv[c], kv.w, d3);
            }
            float e0 = __expf(d0*0.125f);
            float e1 = __expf(d1*0.125f);
            float e2 = __expf(d2*0.125f);
            float e3 = __expf(d3*0.125f);
            float gx0 = (float)((((k0+kk)&63)*2)+1)*0.015625f - 1.0f;
            float es = e0+e1+e2+e3;
            sE += es;
            sY = fmaf(es, gyv, sY);
            sX += e0*gx0 + e1*(gx0+0.03125f) + e2*(gx0+0.0625f) + e3*(gx0+0.09375f);
        }
    }
    size_t base = ((size_t)(b*4+ks)*3)*4096 + q;
    g_part[base        ] = sE;
    g_part[base +  4096] = sX;
    g_part[base +  8192] = sY;
}

__global__ void attn_combine()
{
    int i = blockIdx.x*256 + threadIdx.x;      // 16384
    if (i >= 16384) return;
    int b = i>>12, q = i&4095;
    float sE=0.f, sX=0.f, sY=0.f;
    for (int ks=0; ks<4; ks++) {
        size_t base = ((size_t)(b*4+ks)*3)*4096 + q;
        sE += g_part[base];
        sX += g_part[base+4096];
        sY += g_part[base+8192];
    }
    float inv = 1.0f/sE;
    g_warp[(size_t)(b*2  )*4096 + q] = sX*inv;
    g_warp[(size_t)(b*2+1)*4096 + q] = sY*inv;
}

// ---------------- coarse concat + grid_sample (zero padding) ----------------
__global__ void pack_coarse(const float* __restrict__ f0c, const float* __restrict__ f1c)
{
    int i = blockIdx.x*256 + threadIdx.x;      // 16384
    if (i >= 16384) return;
    int b = i>>12, p = i&4095;
    float wx = g_warp[(size_t)(b*2  )*4096 + p];
    float wy = g_warp[(size_t)(b*2+1)*4096 + p];
    float* xb = g_cat + (size_t)b*136*4096;
    if (blockIdx.y == 0) {
        xb[(size_t)128*4096 + p] = wx;
        xb[(size_t)129*4096 + p] = wy;
#pragma unroll
        for (int c=130;c<136;c++) xb[(size_t)c*4096 + p] = 0.f;
    }

    float fx = (wx + 1.f)*32.f - 0.5f;
    float fy = (wy + 1.f)*32.f - 0.5f;
    float flx = floorf(fx), fly = floorf(fy);
    float ax = fx - flx, ay = fy - fly;
    int xi = (int)flx, yi = (int)fly;
    float vx0 = ((unsigned)xi     < 64u) ? 1.f : 0.f;
    float vx1 = ((unsigned)(xi+1) < 64u) ? 1.f : 0.f;
    float vy0 = ((unsigned)yi     < 64u) ? 1.f : 0.f;
    float vy1 = ((unsigned)(yi+1) < 64u) ? 1.f : 0.f;
    int cx0 = min(max(xi,0),63),   cx1 = min(max(xi+1,0),63);
    int cy0 = min(max(yi,0),63),   cy1 = min(max(yi+1,0),63);
    float w00 = (1.f-ax)*(1.f-ay)*vx0*vy0;
    float w01 = ax*(1.f-ay)*vx1*vy0;
    float w10 = (1.f-ax)*ay*vx0*vy1;
    float w11 = ax*ay*vx1*vy1;
    const float* f1b = f1c + (size_t)b*262144;
    const float* f0b = f0c + (size_t)b*262144;
    int i00 = cy0*64+cx0, i01 = cy0*64+cx1, i10 = cy1*64+cx0, i11 = cy1*64+cx1;
    int cs = blockIdx.y*16;
    for (int c=cs;c<cs+16;c++) {
        const float* fc = f1b + (size_t)c*4096;
        float v = w00*fc[i00] + w01*fc[i01] + w10*fc[i10] + w11*fc[i11];
        xb[(size_t)(64+c)*4096 + p] = v;
        xb[(size_t)c*4096 + p]      = f0b[(size_t)c*4096 + p];
    }
}

// ---------------- direct 3x3 conv, SAME pad, no bias ----------------
// R4 tiling: 32 oc x (8 rows x 16 cols). 256 thr, each 4 oc x 4 px.
// sIn row stride 21 (odd) -> conflict-free scalar LDS:
//   bank delta = 21*dgy + dgx (mod 32); dgy odd -> odd != 0; dgy in {2,4,6} ->
//   {10,20,30} + dgx in {0,+-4,+-8,+-12} never 0 mod 32.
// Optional fused input BN+ReLU (bnm/bni per-channel; nullptr = raw input).
template<int CINP>
__global__ void __launch_bounds__(256) conv3x3_kernel(
    const float* __restrict__ in, const float* __restrict__ wgt,
    float* __restrict__ out,
    const float* __restrict__ bnm, const float* __restrict__ bni,
    int cinReal, int cout, int H, int W)
{
    __shared__ __align__(16) float sIn[8][10][21];
    __shared__ __align__(16) float sW[8][9][32];
    const int HW = H*W;
    const int tilesX = W >> 4;
    const int tx = blockIdx.x % tilesX;
    const int ty = blockIdx.x / tilesX;
    const int ocb = blockIdx.y << 5;
    const int b = blockIdx.z;
    const int tid = threadIdx.x;
    const int pg = tid & 31;
    const int og = tid >> 5;
    const int gx = (pg & 3) << 2;     // local x base: 0,4,8,12
    const int gy = pg >> 2;           // local row 0..7
    const int ocl = og << 2;          // local oc base: 0..28
    const int x0 = tx << 4, y0 = ty << 3;
    const float* inB = in + (size_t)b*CINP*HW;
    const bool doBN = (bnm != nullptr);

    float acc[4][4];
#pragma unroll
    for (int o=0;o<4;o++)
#pragma unroll
        for (int j=0;j<4;j++) acc[o][j] = 0.f;

    for (int c0=0; c0<CINP; c0+=8) {
        __syncthreads();
        // input halo tile 10x18 x 8ic (with optional fused BN+ReLU)
        for (int idx=tid; idx<1440; idx+=256) {
            int ic = idx/180;
            int rem = idx - ic*180;
            int r  = rem/18;
            int cl = rem - r*18;
            int yy = y0-1+r, xx = x0-1+cl;
            float v = 0.f;
            if ((unsigned)yy < (unsigned)H && (unsigned)xx < (unsigned)W) {
                v = inB[(size_t)(c0+ic)*HW + yy*W + xx];
                if (doBN)
                    v = fmaxf((v - bnm[c0+ic])*bni[c0+ic], 0.f);
            }
            sIn[ic][r][cl] = v;
        }
        // weights [ic][k][oc], zero for padded ic
        for (int idx=tid; idx<2304; idx+=256) {
            int ic = idx/288;
            int rem = idx - ic*288;
            int k  = rem >> 5;
            int o  = rem & 31;
            int icg = c0 + ic;
            float v = 0.f;
            if (icg < cinReal)
                v = wgt[((size_t)(ocb+o)*cinReal + icg)*9 + k];
            sW[ic][k][o] = v;
        }
        __syncthreads();
#pragma unroll
        for (int ic=0;ic<8;ic++) {
#pragma unroll
            for (int kh=0;kh<3;kh++) {
                float r[6];
#pragma unroll
                for (int j=0;j<6;j++) r[j] = sIn[ic][gy+kh][gx+j];
#pragma unroll
                for (int kw=0;kw<3;kw++) {
                    float4 w4 = *(const float4*)&sW[ic][kh*3+kw][ocl];
#pragma unroll
                    for (int j=0;j<4;j++) {
                        acc[0][j] = fmaf(w4.x, r[j+kw], acc[0][j]);
                        acc[1][j] = fmaf(w4.y, r[j+kw], acc[1][j]);
                        acc[2][j] = fmaf(w4.z, r[j+kw], acc[2][j]);
                        acc[3][j] = fmaf(w4.w, r[j+kw], acc[3][j]);
                    }
                }
            }
        }
    }
#pragma unroll
    for (int o=0;o<4;o++) {
        float4 v = make_float4(acc[o][0], acc[o][1], acc[o][2], acc[o][3]);
        *(float4*)&out[((size_t)b*cout + (ocb+ocl+o))*HW + (y0+gy)*W + x0+gx] = v;
    }
}

// ---------------- batch-norm: per-channel stats over (B,H,W) ----------------
__global__ void bn_reduce(const float* __restrict__ x, int C, int HW)
{
    const int c = blockIdx.x;
    const int tid = threadIdx.x;
    const int HW4 = HW >> 2;
    float s = 0.f, s2 = 0.f;
    for (int b=0;b<4;b++) {
        const float4* xb = (const float4*)(x + ((size_t)b*C + c)*HW);
        for (int p=tid; p<HW4; p+=256) {
            float4 v = xb[p];
            s  += v.x + v.y + v.z + v.w;
            s2 += v.x*v.x + v.y*v.y + v.z*v.z + v.w*v.w;
        }
    }
    __shared__ float rs[256];
    __shared__ float rq[256];
    rs[tid] = s; rq[tid] = s2;
    __syncthreads();
    for (int off=128; off>0; off>>=1) {
        if (tid < off) { rs[tid]+=rs[tid+off]; rq[tid]+=rq[tid+off]; }
        __syncthreads();
    }
    if (tid == 0) {
        float invN = 1.0f/(4.0f*HW);
        float m = rs[0]*invN;
        float var = rq[0]*invN - m*m;
        g_mean[c] = m;
        g_istd[c] = rsqrtf(var + 1e-5f);
    }
}

__global__ void bn_apply(const float* __restrict__ x, float* __restrict__ y,
                         int cMask, int hwShift)
{
    int idx = blockIdx.x*256 + threadIdx.x;
    int c = (idx >> hwShift) & cMask;
    float v = (x[idx] - g_mean[c]) * g_istd[c];
    y[idx] = fmaxf(v, 0.f);
}

// ---------------- heads (1x1 conv + bias + residual) ----------------
__global__ void head_coarse(const float* __restrict__ w, const float* __restrict__ bias,
                            float* __restrict__ out)
{
    __shared__ float sw[768];
    for (int idx=threadIdx.x; idx<768; idx+=256) sw[idx] = w[idx];
    __syncthreads();
    int i = blockIdx.x*256 + threadIdx.x;     // 16384
    int b = i>>12, p = i&4095;
    const float* xb = g_bufB + (size_t)b*256*4096 + p;
    float a0 = bias[0], a1 = bias[1], a2 = bias[2];
    for (int c=0;c<256;c++) {
        float v = xb[(size_t)c*4096];
        a0 = fmaf(v, sw[c],     a0);
        a1 = fmaf(v, sw[256+c], a1);
        a2 = fmaf(v, sw[512+c], a2);
    }
    out[(size_t)(b*3  )*4096 + p] = g_warp[(size_t)(b*2  )*4096 + p] + a0;
    out[(size_t)(b*3+1)*4096 + p] = g_warp[(size_t)(b*2+1)*4096 + p] + a1;
    out[(size_t)(b*3+2)*4096 + p] = a2;
}

// ---------------- 2x bilinear upsample (half-pixel, edge-clamped) ----------------
__global__ void upsample_kernel(const float* __restrict__ cm)
{
    int idx = blockIdx.x*256 + threadIdx.x;   // 196608
    if (idx >= 196608) return;
    int p  = idx & 16383;
    int bc = idx >> 14;
    int ox = p & 127, oy = p >> 7;
    float sx = 0.5f*ox - 0.25f;
    float sy = 0.5f*oy - 0.25f;
    float fx = floorf(sx), fy = floorf(sy);
    float ax = sx - fx, ay = sy - fy;
    int x0 = (int)fx, y0 = (int)fy;
    int x0c = max(x0,0), x1c = min(x0+1,63);
    int y0c = max(y0,0), y1c = min(y0+1,63);
    const float* inb = cm + (size_t)bc*4096;
    float v00 = inb[y0c*64+x0c], v01 = inb[y0c*64+x1c];
    float v10 = inb[y1c*64+x0c], v11 = inb[y1c*64+x1c];
    g_up[idx] = (1.f-ay)*((1.f-ax)*v00 + ax*v01) + ay*((1.f-ax)*v10 + ax*v11);
}

// ---------------- fine concat + grid_sample ----------------
__global__ void pack_fine(const float* __restrict__ f0f, const float* __restrict__ f1f)
{
    int i = blockIdx.x*256 + threadIdx.x;     // 65536
    if (i >= 65536) return;
    int b = i>>14, p = i&16383;
    float wx = g_up[(size_t)(b*3  )*16384 + p];
    float wy = g_up[(size_t)(b*3+1)*16384 + p];
    float* yb = g_cat + (size_t)b*56*16384;
    if (blockIdx.y == 0) {
        yb[(size_t)48*16384 + p] = wx;
        yb[(size_t)49*16384 + p] = wy;
#pragma unroll
        for (int c=50;c<56;c++) yb[(size_t)c*16384 + p] = 0.f;
    }

    float fx = (wx + 1.f)*64.f - 0.5f;
    float fy = (wy + 1.f)*64.f - 0.5f;
    float flx = floorf(fx), fly = floorf(fy);
    float ax = fx - flx, ay = fy - fly;
    int xi = (int)flx, yi = (int)fly;
    float vx0 = ((unsigned)xi     < 128u) ? 1.f : 0.f;
    float vx1 = ((unsigned)(xi+1) < 128u) ? 1.f : 0.f;
    float vy0 = ((unsigned)yi     < 128u) ? 1.f : 0.f;
    float vy1 = ((unsigned)(yi+1) < 128u) ? 1.f : 0.f;
    int cx0 = min(max(xi,0),127),  cx1 = min(max(xi+1,0),127);
    int cy0 = min(max(yi,0),127),  cy1 = min(max(yi+1,0),127);
    float w00 = (1.f-ax)*(1.f-ay)*vx0*vy0;
    float w01 = ax*(1.f-ay)*vx1*vy0;
    float w10 = (1.f-ax)*ay*vx0*vy1;
    float w11 = ax*ay*vx1*vy1;
    const float* f1b = f1f + (size_t)b*24*16384;
    const float* f0b = f0f + (size_t)b*24*16384;
    int i00 = cy0*128+cx0, i01 = cy0*128+cx1, i10 = cy1*128+cx0, i11 = cy1*128+cx1;
    int cs = blockIdx.y*6;
    for (int c=cs;c<cs+6;c++) {
        const float* fc = f1b + (size_t)c*16384;
        float v = w00*fc[i00] + w01*fc[i01] + w10*fc[i10] + w11*fc[i11];
        yb[(size_t)(24+c)*16384 + p] = v;
        yb[(size_t)c*16384 + p]      = f0b[(size_t)c*16384 + p];
    }
}

__global__ void head_fine(const float* __restrict__ w, const float* __restrict__ bias,
                          float* __restrict__ out)
{
    __shared__ float sw[192];
    for (int idx=threadIdx.x; idx<192; idx+=256) sw[idx] = w[idx];
    __syncthreads();
    int i = blockIdx.x*256 + threadIdx.x;     // 65536
    int b = i>>14, p = i&16383;
    const float* yb = g_bufB + (size_t)b*64*16384 + p;
    float a0 = bias[0], a1 = bias[1], a2 = bias[2];
    for (int c=0;c<64;c++) {
        float v = yb[(size_t)c*16384];
        a0 = fmaf(v, sw[c],      a0);
        a1 = fmaf(v, sw[64+c],   a1);
        a2 = fmaf(v, sw[128+c],  a2);
    }
    out[(size_t)(b*3  )*16384 + p] = g_up[(size_t)(b*3  )*16384 + p] + a0;
    out[(size_t)(b*3+1)*16384 + p] = g_up[(size_t)(b*3+1)*16384 + p] + a1;
    out[(size_t)(b*3+2)*16384 + p] = g_up[(size_t)(b*3+2)*16384 + p] + a2;
}

// ---------------- launch ----------------
extern "C" void kernel_launch(void* const* d_in, const int* in_sizes, int n_in,
                              void* d_out, int out_size)
{
    const float* f0c = (const float*)d_in[0];
    const float* f1c = (const float*)d_in[1];
    const float* f0f = (const float*)d_in[2];
    const float* f1f = (const float*)d_in[3];
    const float* cw1 = (const float*)d_in[4];
    const float* cw2 = (const float*)d_in[5];
    const float* cw3 = (const float*)d_in[6];
    const float* cw4 = (const float*)d_in[7];
    const float* cw5 = (const float*)d_in[8];
    const float* cb5 = (const float*)d_in[9];
    const float* fw1 = (const float*)d_in[10];
    const float* fw2 = (const float*)d_in[11];
    const float* fw3 = (const float*)d_in[12];
    const float* fw4 = (const float*)d_in[13];
    const float* fw5 = (const float*)d_in[14];
    const float* fb5 = (const float*)d_in[15];

    float *pCat, *pA, *pB, *pM, *pI;
    cudaGetSymbolAddress((void**)&pCat, g_cat);
    cudaGetSymbolAddress((void**)&pA,   g_bufA);
    cudaGetSymbolAddress((void**)&pB,   g_bufB);
    cudaGetSymbolAddress((void**)&pM,   g_mean);
    cudaGetSymbolAddress((void**)&pI,   g_istd);

    float* outC = (float*)d_out;          // (4,3,64,64)
    float* outF = outC + 49152;           // (4,3,128,128)

    // coarse attention -> warp field
    attn_kernel<<<dim3(16,4,4),256>>>(f0c, f1c);
    attn_combine<<<64,256>>>();
    pack_coarse<<<dim3(64,4),256>>>(f0c, f1c);

    // coarse conv tower: conv -> stats; BN+ReLU fused into the NEXT conv's load
    // grid: (tilesX*tilesY, cout/32, B) = (32, 8, 4) -> 1024 blocks
    conv3x3_kernel<136><<<dim3(32,8,4),256>>>(pCat, cw1, pA, nullptr, nullptr, 130, 256, 64, 64);
    bn_reduce<<<256,256>>>(pA, 256, 4096);
    conv3x3_kernel<256><<<dim3(32,8,4),256>>>(pA, cw2, pB, pM, pI, 256, 256, 64, 64);
    bn_reduce<<<256,256>>>(pB, 256, 4096);
    conv3x3_kernel<256><<<dim3(32,8,4),256>>>(pB, cw3, pA, pM, pI, 256, 256, 64, 64);
    bn_reduce<<<256,256>>>(pA, 256, 4096);
    conv3x3_kernel<256><<<dim3(32,8,4),256>>>(pA, cw4, pB, pM, pI, 256, 256, 64, 64);
    bn_reduce<<<256,256>>>(pB, 256, 4096);
    bn_apply<<<16384,256>>>(pB, pB, 255, 12);     // materialize BN for head

    head_coarse<<<64,256>>>(cw5, cb5, outC);

    // fine stage
    upsample_kernel<<<768,256>>>(outC);
    pack_fine<<<dim3(256,4),256>>>(f0f, f1f);

    // fine grid: (8*16, 64/32, 4) = (128, 2, 4) -> 1024 blocks
    conv3x3_kernel<56><<<dim3(128,2,4),256>>>(pCat, fw1, pA, nullptr, nullptr, 50, 64, 128, 128);
    bn_reduce<<<64,256>>>(pA, 64, 16384);
    conv3x3_kernel<64><<<dim3(128,2,4),256>>>(pA, fw2, pB, pM, pI, 64, 64, 128, 128);
    bn_reduce<<<64,256>>>(pB, 64, 16384);
    conv3x3_kernel<64><<<dim3(128,2,4),256>>>(pB, fw3, pA, pM, pI, 64, 64, 128, 128);
    bn_reduce<<<64,256>>>(pA, 64, 16384);
    conv3x3_kernel<64><<<dim3(128,2,4),256>>>(pA, fw4, pB, pM, pI, 64, 64, 128, 128);
    bn_reduce<<<64,256>>>(pB, 64, 16384);
    bn_apply<<<16384,256>>>(pB, pB, 63, 14);      // materialize BN for head

    head_fine<<<256,256>>>(fw5, fb5, outF);
}

// round 9
// speedup vs baseline: 1.1952x; 1.1450x over previous
#include <cuda_runtime.h>
#include <cstdint>
#include <math.h>

// ---------------- scratch (static __device__, no allocation) ----------------
__device__ float g_part[4*4*3*4096];     // attention partials [b][ks][3][q]
__device__ float g_warp[4*2*4096];       // coarse_warp [b][2][p]
__device__ float g_cat[3670016];         // concat input: coarse 4*136*4096 / fine 4*56*16384
__device__ float g_bufA[4194304];        // conv ping
__device__ float g_bufB[4194304];        // conv pong
__device__ float g_up[4*3*16384];        // upsampled coarse matches
__device__ float g_mean[256];
__device__ float g_istd[256];

// ---------------- cp.async helpers ----------------
__device__ __forceinline__ uint32_t smem_u32(const void* p) {
    return (uint32_t)__cvta_generic_to_shared(p);
}
__device__ __forceinline__ void cp_async4(uint32_t dst, const void* src, int srcsz) {
    asm volatile("cp.async.ca.shared.global [%0], [%1], 4, %2;\n"
                 :: "r"(dst), "l"(src), "r"(srcsz));
}
__device__ __forceinline__ void cp_commit() {
    asm volatile("cp.async.commit_group;\n");
}
__device__ __forceinline__ void cp_wait1() {
    asm volatile("cp.async.wait_group 1;\n");
}
__device__ __forceinline__ void cp_wait0() {
    asm volatile("cp.async.wait_group 0;\n");
}

// ---------------- fused correlation-softmax-expectation ----------------
__global__ void __launch_bounds__(256) attn_kernel(const float* __restrict__ f0,
                                                   const float* __restrict__ f1)
{
    __shared__ __align__(16) float sK[64][64];
    const int qb = blockIdx.x, ks = blockIdx.y, b = blockIdx.z;
    const int q = qb*256 + threadIdx.x;
    const float* f0b = f0 + (size_t)b*262144;
    const float* f1b = f1 + (size_t)b*262144;
    float qv[64];
#pragma unroll
    for (int c=0;c<64;c++) qv[c] = f0b[c*4096 + q];
    float sE=0.f, sX=0.f, sY=0.f;
    const int kbase = ks*1024;
    for (int t=0; t<1024; t+=64) {
        __syncthreads();
        const int k0 = kbase + t;
        for (int idx=threadIdx.x; idx<4096; idx+=256) {
            int c = idx>>6, kk = idx&63;
            sK[c][kk] = f1b[c*4096 + k0 + kk];
        }
        __syncthreads();
        const float gyv = (float)((k0>>6)*2 + 1)*0.015625f - 1.0f;
        for (int kk=0; kk<64; kk+=4) {
            float d0=0.f,d1=0.f,d2=0.f,d3=0.f;
#pragma unroll
            for (int c=0;c<64;c++) {
                float4 kv = *(const float4*)&sK[c][kk];
                d0 = fmaf(qv[c], kv.x, d0);
                d1 = fmaf(qv[c], kv.y, d1);
                d2 = fmaf(qv[c], kv.z, d2);
                d3 = fmaf(qv[c], kv.w, d3);
            }
            float e0 = __expf(d0*0.125f);
            float e1 = __expf(d1*0.125f);
            float e2 = __expf(d2*0.125f);
            float e3 = __expf(d3*0.125f);
            float gx0 = (float)((((k0+kk)&63)*2)+1)*0.015625f - 1.0f;
            float es = e0+e1+e2+e3;
            sE += es;
            sY = fmaf(es, gyv, sY);
            sX += e0*gx0 + e1*(gx0+0.03125f) + e2*(gx0+0.0625f) + e3*(gx0+0.09375f);
        }
    }
    size_t base = ((size_t)(b*4+ks)*3)*4096 + q;
    g_part[base        ] = sE;
    g_part[base +  4096] = sX;
    g_part[base +  8192] = sY;
}

__global__ void attn_combine()
{
    int i = blockIdx.x*256 + threadIdx.x;      // 16384
    if (i >= 16384) return;
    int b = i>>12, q = i&4095;
    float sE=0.f, sX=0.f, sY=0.f;
    for (int ks=0; ks<4; ks++) {
        size_t base = ((size_t)(b*4+ks)*3)*4096 + q;
        sE += g_part[base];
        sX += g_part[base+4096];
        sY += g_part[base+8192];
    }
    float inv = 1.0f/sE;
    g_warp[(size_t)(b*2  )*4096 + q] = sX*inv;
    g_warp[(size_t)(b*2+1)*4096 + q] = sY*inv;
}

// ---------------- coarse concat + grid_sample (zero padding) ----------------
__global__ void pack_coarse(const float* __restrict__ f0c, const float* __restrict__ f1c)
{
    int i = blockIdx.x*256 + threadIdx.x;      // 16384
    if (i >= 16384) return;
    int b = i>>12, p = i&4095;
    float wx = g_warp[(size_t)(b*2  )*4096 + p];
    float wy = g_warp[(size_t)(b*2+1)*4096 + p];
    float* xb = g_cat + (size_t)b*136*4096;
    if (blockIdx.y == 0) {
        xb[(size_t)128*4096 + p] = wx;
        xb[(size_t)129*4096 + p] = wy;
#pragma unroll
        for (int c=130;c<136;c++) xb[(size_t)c*4096 + p] = 0.f;
    }

    float fx = (wx + 1.f)*32.f - 0.5f;
    float fy = (wy + 1.f)*32.f - 0.5f;
    float flx = floorf(fx), fly = floorf(fy);
    float ax = fx - flx, ay = fy - fly;
    int xi = (int)flx, yi = (int)fly;
    float vx0 = ((unsigned)xi     < 64u) ? 1.f : 0.f;
    float vx1 = ((unsigned)(xi+1) < 64u) ? 1.f : 0.f;
    float vy0 = ((unsigned)yi     < 64u) ? 1.f : 0.f;
    float vy1 = ((unsigned)(yi+1) < 64u) ? 1.f : 0.f;
    int cx0 = min(max(xi,0),63),   cx1 = min(max(xi+1,0),63);
    int cy0 = min(max(yi,0),63),   cy1 = min(max(yi+1,0),63);
    float w00 = (1.f-ax)*(1.f-ay)*vx0*vy0;
    float w01 = ax*(1.f-ay)*vx1*vy0;
    float w10 = (1.f-ax)*ay*vx0*vy1;
    float w11 = ax*ay*vx1*vy1;
    const float* f1b = f1c + (size_t)b*262144;
    const float* f0b = f0c + (size_t)b*262144;
    int i00 = cy0*64+cx0, i01 = cy0*64+cx1, i10 = cy1*64+cx0, i11 = cy1*64+cx1;
    int cs = blockIdx.y*16;
    for (int c=cs;c<cs+16;c++) {
        const float* fc = f1b + (size_t)c*4096;
        float v = w00*fc[i00] + w01*fc[i01] + w10*fc[i10] + w11*fc[i11];
        xb[(size_t)(64+c)*4096 + p] = v;
        xb[(size_t)c*4096 + p]      = f0b[(size_t)c*4096 + p];
    }
}

// ---------------- direct 3x3 conv, SAME pad, no bias ----------------
// R5 tiling: 32 oc x (8 rows x 32 cols). 256 thr, each 4 oc x 8 px.
// Warp: gy = lane>>2 (0..7), gx = (lane&3)*8. sIn row stride 35:
//   bank delta = 35*dgy + dgx = 3*dgy + dgx (mod 32), dgx in {0,±8,±16,24}
//   -> exhaustively nonzero for all dgy in 1..7 (verified).
// Double-buffered cp.async staging of input halo + weights.
template<int CINP>
__global__ void __launch_bounds__(256) conv3x3_kernel(
    const float* __restrict__ in, const float* __restrict__ wgt,
    float* __restrict__ out, int cinReal, int cout, int H, int W)
{
    __shared__ __align__(16) float sIn[2][8][10][35];
    __shared__ __align__(16) float sW[2][8][9][32];
    const int HW = H*W;
    const int tilesX = W >> 5;
    const int tx = blockIdx.x % tilesX;
    const int ty = blockIdx.x / tilesX;
    const int ocb = blockIdx.y << 5;
    const int b = blockIdx.z;
    const int tid = threadIdx.x;
    const int lane = tid & 31;
    const int wid = tid >> 5;
    const int gx = (lane & 3) << 3;   // x base: 0,8,16,24
    const int gy = lane >> 2;         // row 0..7
    const int ocl = wid << 2;         // local oc base 0..28
    const int x0 = tx << 5, y0 = ty << 3;
    const float* inB = in + (size_t)b*CINP*HW;
    constexpr int NCH = CINP/8;

    // precompute staging coordinates for this thread (same every chunk)
    // input: 2720 = 8ic * 10r * 34cl -> ~10.6 per thread
    // weights: 2304 = 8ic * 9k * 32oc -> 9 per thread

    auto stage = [&](int buf, int c0) {
        for (int idx=tid; idx<2720; idx+=256) {
            int ic = idx/340;
            int rem = idx - ic*340;
            int r  = rem/34;
            int cl = rem - r*34;
            int yy = y0-1+r, xx = x0-1+cl;
            bool ok = ((unsigned)yy < (unsigned)H) && ((unsigned)xx < (unsigned)W);
            int yc = min(max(yy,0),H-1), xc = min(max(xx,0),W-1);
            const float* src = inB + (size_t)(c0+ic)*HW + yc*W + xc;
            cp_async4(smem_u32(&sIn[buf][ic][r][cl]), src, ok ? 4 : 0);
        }
        for (int idx=tid; idx<2304; idx+=256) {
            int ic = idx/288;
            int rem = idx - ic*288;
            int k  = rem >> 5;
            int o  = rem & 31;
            int icg = c0 + ic;
            int icc = min(icg, cinReal-1);
            const float* src = wgt + ((size_t)(ocb+o)*cinReal + icc)*9 + k;
            cp_async4(smem_u32(&sW[buf][ic][k][o]), src, (icg < cinReal) ? 4 : 0);
        }
        cp_commit();
    };

    float acc[4][8];
#pragma unroll
    for (int o=0;o<4;o++)
#pragma unroll
        for (int j=0;j<8;j++) acc[o][j] = 0.f;

    stage(0, 0);

    for (int ci=0; ci<NCH; ci++) {
        if (ci+1 < NCH) {
            stage((ci+1)&1, (ci+1)*8);
            cp_wait1();
        } else {
            cp_wait0();
        }
        __syncthreads();
        const int buf = ci & 1;
#pragma unroll
        for (int ic=0;ic<8;ic++) {
#pragma unroll
            for (int kh=0;kh<3;kh++) {
                float r[10];
#pragma unroll
                for (int j=0;j<10;j++) r[j] = sIn[buf][ic][gy+kh][gx+j];
#pragma unroll
                for (int kw=0;kw<3;kw++) {
                    float4 w4 = *(const float4*)&sW[buf][ic][kh*3+kw][ocl];
#pragma unroll
                    for (int j=0;j<8;j++) {
                        acc[0][j] = fmaf(w4.x, r[j+kw], acc[0][j]);
                        acc[1][j] = fmaf(w4.y, r[j+kw], acc[1][j]);
                        acc[2][j] = fmaf(w4.z, r[j+kw], acc[2][j]);
                        acc[3][j] = fmaf(w4.w, r[j+kw], acc[3][j]);
                    }
                }
            }
        }
        __syncthreads();
    }
#pragma unroll
    for (int o=0;o<4;o++) {
        float* op = &out[((size_t)b*cout + (ocb+ocl+o))*HW + (y0+gy)*W + x0+gx];
        float4 v0 = make_float4(acc[o][0], acc[o][1], acc[o][2], acc[o][3]);
        float4 v1 = make_float4(acc[o][4], acc[o][5], acc[o][6], acc[o][7]);
        *(float4*)op       = v0;
        *(float4*)(op + 4) = v1;
    }
}

// ---------------- batch-norm: per-channel stats over (B,H,W) ----------------
__global__ void bn_reduce(const float* __restrict__ x, int C, int HW)
{
    const int c = blockIdx.x;
    const int tid = threadIdx.x;
    const int HW4 = HW >> 2;
    float s = 0.f, s2 = 0.f;
    for (int b=0;b<4;b++) {
        const float4* xb = (const float4*)(x + ((size_t)b*C + c)*HW);
        for (int p=tid; p<HW4; p+=256) {
            float4 v = xb[p];
            s  += v.x + v.y + v.z + v.w;
            s2 += v.x*v.x + v.y*v.y + v.z*v.z + v.w*v.w;
        }
    }
    __shared__ float rs[256];
    __shared__ float rq[256];
    rs[tid] = s; rq[tid] = s2;
    __syncthreads();
    for (int off=128; off>0; off>>=1) {
        if (tid < off) { rs[tid]+=rs[tid+off]; rq[tid]+=rq[tid+off]; }
        __syncthreads();
    }
    if (tid == 0) {
        float invN = 1.0f/(4.0f*HW);
        float m = rs[0]*invN;
        float var = rq[0]*invN - m*m;
        g_mean[c] = m;
        g_istd[c] = rsqrtf(var + 1e-5f);
    }
}

// in-place BN + ReLU, float4 vectorized (HW multiple of 4)
__global__ void bn_apply(float* __restrict__ x, int cMask, int hwShift)
{
    int idx = blockIdx.x*256 + threadIdx.x;   // element/4 index
    int c = (idx >> (hwShift-2)) & cMask;
    float m = g_mean[c], is = g_istd[c];
    float4 v = ((float4*)x)[idx];
    v.x = fmaxf((v.x - m)*is, 0.f);
    v.y = fmaxf((v.y - m)*is, 0.f);
    v.z = fmaxf((v.z - m)*is, 0.f);
    v.w = fmaxf((v.w - m)*is, 0.f);
    ((float4*)x)[idx] = v;
}

// ---------------- heads (1x1 conv + bias + residual) ----------------
__global__ void head_coarse(const float* __restrict__ w, const float* __restrict__ bias,
                            float* __restrict__ out)
{
    __shared__ float sw[768];
    for (int idx=threadIdx.x; idx<768; idx+=256) sw[idx] = w[idx];
    __syncthreads();
    int i = blockIdx.x*256 + threadIdx.x;     // 16384
    int b = i>>12, p = i&4095;
    const float* xb = g_bufB + (size_t)b*256*4096 + p;
    float a0 = bias[0], a1 = bias[1], a2 = bias[2];
    for (int c=0;c<256;c++) {
        float v = xb[(size_t)c*4096];
        a0 = fmaf(v, sw[c],     a0);
        a1 = fmaf(v, sw[256+c], a1);
        a2 = fmaf(v, sw[512+c], a2);
    }
    out[(size_t)(b*3  )*4096 + p] = g_warp[(size_t)(b*2  )*4096 + p] + a0;
    out[(size_t)(b*3+1)*4096 + p] = g_warp[(size_t)(b*2+1)*4096 + p] + a1;
    out[(size_t)(b*3+2)*4096 + p] = a2;
}

// ---------------- 2x bilinear upsample (half-pixel, edge-clamped) ----------------
__global__ void upsample_kernel(const float* __restrict__ cm)
{
    int idx = blockIdx.x*256 + threadIdx.x;   // 196608
    if (idx >= 196608) return;
    int p  = idx & 16383;
    int bc = idx >> 14;
    int ox = p & 127, oy = p >> 7;
    float sx = 0.5f*ox - 0.25f;
    float sy = 0.5f*oy - 0.25f;
    float fx = floorf(sx), fy = floorf(sy);
    float ax = sx - fx, ay = sy - fy;
    int x0 = (int)fx, y0 = (int)fy;
    int x0c = max(x0,0), x1c = min(x0+1,63);
    int y0c = max(y0,0), y1c = min(y0+1,63);
    const float* inb = cm + (size_t)bc*4096;
    float v00 = inb[y0c*64+x0c], v01 = inb[y0c*64+x1c];
    float v10 = inb[y1c*64+x0c], v11 = inb[y1c*64+x1c];
    g_up[idx] = (1.f-ay)*((1.f-ax)*v00 + ax*v01) + ay*((1.f-ax)*v10 + ax*v11);
}

// ---------------- fine concat + grid_sample ----------------
__global__ void pack_fine(const float* __restrict__ f0f, const float* __restrict__ f1f)
{
    int i = blockIdx.x*256 + threadIdx.x;     // 65536
    if (i >= 65536) return;
    int b = i>>14, p = i&16383;
    float wx = g_up[(size_t)(b*3  )*16384 + p];
    float wy = g_up[(size_t)(b*3+1)*16384 + p];
    float* yb = g_cat + (size_t)b*56*16384;
    if (blockIdx.y == 0) {
        yb[(size_t)48*16384 + p] = wx;
        yb[(size_t)49*16384 + p] = wy;
#pragma unroll
        for (int c=50;c<56;c++) yb[(size_t)c*16384 + p] = 0.f;
    }

    float fx = (wx + 1.f)*64.f - 0.5f;
    float fy = (wy + 1.f)*64.f - 0.5f;
    float flx = floorf(fx), fly = floorf(fy);
    float ax = fx - flx, ay = fy - fly;
    int xi = (int)flx, yi = (int)fly;
    float vx0 = ((unsigned)xi     < 128u) ? 1.f : 0.f;
    float vx1 = ((unsigned)(xi+1) < 128u) ? 1.f : 0.f;
    float vy0 = ((unsigned)yi     < 128u) ? 1.f : 0.f;
    float vy1 = ((unsigned)(yi+1) < 128u) ? 1.f : 0.f;
    int cx0 = min(max(xi,0),127),  cx1 = min(max(xi+1,0),127);
    int cy0 = min(max(yi,0),127),  cy1 = min(max(yi+1,0),127);
    float w00 = (1.f-ax)*(1.f-ay)*vx0*vy0;
    float w01 = ax*(1.f-ay)*vx1*vy0;
    float w10 = (1.f-ax)*ay*vx0*vy1;
    float w11 = ax*ay*vx1*vy1;
    const float* f1b = f1f + (size_t)b*24*16384;
    const float* f0b = f0f + (size_t)b*24*16384;
    int i00 = cy0*128+cx0, i01 = cy0*128+cx1, i10 = cy1*128+cx0, i11 = cy1*128+cx1;
    int cs = blockIdx.y*6;
    for (int c=cs;c<cs+6;c++) {
        const float* fc = f1b + (size_t)c*16384;
        float v = w00*fc[i00] + w01*fc[i01] + w10*fc[i10] + w11*fc[i11];
        yb[(size_t)(24+c)*16384 + p] = v;
        yb[(size_t)c*16384 + p]      = f0b[(size_t)c*16384 + p];
    }
}

__global__ void head_fine(const float* __restrict__ w, const float* __restrict__ bias,
                          float* __restrict__ out)
{
    __shared__ float sw[192];
    for (int idx=threadIdx.x; idx<192; idx+=256) sw[idx] = w[idx];
    __syncthreads();
    int i = blockIdx.x*256 + threadIdx.x;     // 65536
    int b = i>>14, p = i&16383;
    const float* yb = g_bufB + (size_t)b*64*16384 + p;
    float a0 = bias[0], a1 = bias[1], a2 = bias[2];
    for (int c=0;c<64;c++) {
        float v = yb[(size_t)c*16384];
        a0 = fmaf(v, sw[c],      a0);
        a1 = fmaf(v, sw[64+c],   a1);
        a2 = fmaf(v, sw[128+c],  a2);
    }
    out[(size_t)(b*3  )*16384 + p] = g_up[(size_t)(b*3  )*16384 + p] + a0;
    out[(size_t)(b*3+1)*16384 + p] = g_up[(size_t)(b*3+1)*16384 + p] + a1;
    out[(size_t)(b*3+2)*16384 + p] = g_up[(size_t)(b*3+2)*16384 + p] + a2;
}

// ---------------- launch ----------------
extern "C" void kernel_launch(void* const* d_in, const int* in_sizes, int n_in,
                              void* d_out, int out_size)
{
    const float* f0c = (const float*)d_in[0];
    const float* f1c = (const float*)d_in[1];
    const float* f0f = (const float*)d_in[2];
    const float* f1f = (const float*)d_in[3];
    const float* cw1 = (const float*)d_in[4];
    const float* cw2 = (const float*)d_in[5];
    const float* cw3 = (const float*)d_in[6];
    const float* cw4 = (const float*)d_in[7];
    const float* cw5 = (const float*)d_in[8];
    const float* cb5 = (const float*)d_in[9];
    const float* fw1 = (const float*)d_in[10];
    const float* fw2 = (const float*)d_in[11];
    const float* fw3 = (const float*)d_in[12];
    const float* fw4 = (const float*)d_in[13];
    const float* fw5 = (const float*)d_in[14];
    const float* fb5 = (const float*)d_in[15];

    float *pCat, *pA, *pB;
    cudaGetSymbolAddress((void**)&pCat, g_cat);
    cudaGetSymbolAddress((void**)&pA,   g_bufA);
    cudaGetSymbolAddress((void**)&pB,   g_bufB);

    float* outC = (float*)d_out;          // (4,3,64,64)
    float* outF = outC + 49152;           // (4,3,128,128)

    // coarse attention -> warp field
    attn_kernel<<<dim3(16,4,4),256>>>(f0c, f1c);
    attn_combine<<<64,256>>>();
    pack_coarse<<<dim3(64,4),256>>>(f0c, f1c);

    // coarse conv tower: conv -> stats -> in-place BN+ReLU
    // conv grid: (tilesX*tilesY, cout/32, B) = (2*8, 8, 4) = 512 blocks
    conv3x3_kernel<136><<<dim3(16,8,4),256>>>(pCat, cw1, pA, 130, 256, 64, 64);
    bn_reduce<<<256,256>>>(pA, 256, 4096);
    bn_apply<<<4096,256>>>(pA, 255, 12);
    conv3x3_kernel<256><<<dim3(16,8,4),256>>>(pA, cw2, pB, 256, 256, 64, 64);
    bn_reduce<<<256,256>>>(pB, 256, 4096);
    bn_apply<<<4096,256>>>(pB, 255, 12);
    conv3x3_kernel<256><<<dim3(16,8,4),256>>>(pB, cw3, pA, 256, 256, 64, 64);
    bn_reduce<<<256,256>>>(pA, 256, 4096);
    bn_apply<<<4096,256>>>(pA, 255, 12);
    conv3x3_kernel<256><<<dim3(16,8,4),256>>>(pA, cw4, pB, 256, 256, 64, 64);
    bn_reduce<<<256,256>>>(pB, 256, 4096);
    bn_apply<<<4096,256>>>(pB, 255, 12);

    head_coarse<<<64,256>>>(cw5, cb5, outC);

    // fine stage
    upsample_kernel<<<768,256>>>(outC);
    pack_fine<<<dim3(256,4),256>>>(f0f, f1f);

    // fine conv grid: (4*16, 2, 4) = 512 blocks
    conv3x3_kernel<56><<<dim3(64,2,4),256>>>(pCat, fw1, pA, 50, 64, 128, 128);
    bn_reduce<<<64,256>>>(pA, 64, 16384);
    bn_apply<<<4096,256>>>(pA, 63, 14);
    conv3x3_kernel<64><<<dim3(64,2,4),256>>>(pA, fw2, pB, 64, 64, 128, 128);
    bn_reduce<<<64,256>>>(pB, 64, 16384);
    bn_apply<<<4096,256>>>(pB, 63, 14);
    conv3x3_kernel<64><<<dim3(64,2,4),256>>>(pB, fw3, pA, 64, 64, 128, 128);
    bn_reduce<<<64,256>>>(pA, 64, 16384);
    bn_apply<<<4096,256>>>(pA, 63, 14);
    conv3x3_kernel<64><<<dim3(64,2,4),256>>>(pA, fw4, pB, 64, 64, 128, 128);
    bn_reduce<<<64,256>>>(pB, 64, 16384);
    bn_apply<<<4096,256>>>(pB, 63, 14);

    head_fine<<<256,256>>>(fw5, fb5, outF);
}

// round 10
// speedup vs baseline: 1.2203x; 1.0209x over previous
#include <cuda_runtime.h>
#include <cstdint>
#include <math.h>

typedef unsigned long long ull;

// ---------------- scratch (static __device__, no allocation) ----------------
__device__ float g_part[4*4*3*4096];     // attention partials [b][ks][3][q]
__device__ float g_warp[4*2*4096];       // coarse_warp [b][2][p]
__device__ float g_cat[3670016];         // concat input: coarse 4*136*4096 / fine 4*56*16384
__device__ float g_bufA[4194304];        // conv ping
__device__ float g_bufB[4194304];        // conv pong
__device__ float g_up[4*3*16384];        // upsampled coarse matches
__device__ float g_mean[256];
__device__ float g_istd[256];

// ---------------- cp.async helpers ----------------
__device__ __forceinline__ uint32_t smem_u32(const void* p) {
    return (uint32_t)__cvta_generic_to_shared(p);
}
__device__ __forceinline__ void cp_async4(uint32_t dst, const void* src, int srcsz) {
    asm volatile("cp.async.ca.shared.global [%0], [%1], 4, %2;\n"
                 :: "r"(dst), "l"(src), "r"(srcsz));
}
__device__ __forceinline__ void cp_commit() {
    asm volatile("cp.async.commit_group;\n");
}
__device__ __forceinline__ void cp_wait1() {
    asm volatile("cp.async.wait_group 1;\n");
}
__device__ __forceinline__ void cp_wait0() {
    asm volatile("cp.async.wait_group 0;\n");
}

// ---------------- packed f32x2 helpers (sm_10x FFMA2) ----------------
__device__ __forceinline__ ull pk2(float lo, float hi) {
    ull r;
    asm("mov.b64 %0, {%1, %2};" : "=l"(r) : "f"(lo), "f"(hi));
    return r;
}
__device__ __forceinline__ void unpk2(ull v, float& lo, float& hi) {
    asm("mov.b64 {%0, %1}, %2;" : "=f"(lo), "=f"(hi) : "l"(v));
}
__device__ __forceinline__ void fma2(ull& d, ull a, ull b) {
    asm("fma.rn.f32x2 %0, %1, %2, %0;" : "+l"(d) : "l"(a), "l"(b));
}

// ---------------- fused correlation-softmax-expectation ----------------
__global__ void __launch_bounds__(256) attn_kernel(const float* __restrict__ f0,
                                                   const float* __restrict__ f1)
{
    __shared__ __align__(16) float sK[64][64];
    const int qb = blockIdx.x, ks = blockIdx.y, b = blockIdx.z;
    const int q = qb*256 + threadIdx.x;
    const float* f0b = f0 + (size_t)b*262144;
    const float* f1b = f1 + (size_t)b*262144;
    float qv[64];
#pragma unroll
    for (int c=0;c<64;c++) qv[c] = f0b[c*4096 + q];
    float sE=0.f, sX=0.f, sY=0.f;
    const int kbase = ks*1024;
    for (int t=0; t<1024; t+=64) {
        __syncthreads();
        const int k0 = kbase + t;
        for (int idx=threadIdx.x; idx<4096; idx+=256) {
            int c = idx>>6, kk = idx&63;
            sK[c][kk] = f1b[c*4096 + k0 + kk];
        }
        __syncthreads();
        const float gyv = (float)((k0>>6)*2 + 1)*0.015625f - 1.0f;
        for (int kk=0; kk<64; kk+=4) {
            float d0=0.f,d1=0.f,d2=0.f,d3=0.f;
#pragma unroll
            for (int c=0;c<64;c++) {
                float4 kv = *(const float4*)&sK[c][kk];
                d0 = fmaf(qv[c], kv.x, d0);
                d1 = fmaf(qv[c], kv.y, d1);
                d2 = fmaf(qv[c], kv.z, d2);
                d3 = fmaf(qv[c], kv.w, d3);
            }
            float e0 = __expf(d0*0.125f);
            float e1 = __expf(d1*0.125f);
            float e2 = __expf(d2*0.125f);
            float e3 = __expf(d3*0.125f);
            float gx0 = (float)((((k0+kk)&63)*2)+1)*0.015625f - 1.0f;
            float es = e0+e1+e2+e3;
            sE += es;
            sY = fmaf(es, gyv, sY);
            sX += e0*gx0 + e1*(gx0+0.03125f) + e2*(gx0+0.0625f) + e3*(gx0+0.09375f);
        }
    }
    size_t base = ((size_t)(b*4+ks)*3)*4096 + q;
    g_part[base        ] = sE;
    g_part[base +  4096] = sX;
    g_part[base +  8192] = sY;
}

__global__ void attn_combine()
{
    int i = blockIdx.x*256 + threadIdx.x;      // 16384
    if (i >= 16384) return;
    int b = i>>12, q = i&4095;
    float sE=0.f, sX=0.f, sY=0.f;
    for (int ks=0; ks<4; ks++) {
        size_t base = ((size_t)(b*4+ks)*3)*4096 + q;
        sE += g_part[base];
        sX += g_part[base+4096];
        sY += g_part[base+8192];
    }
    float inv = 1.0f/sE;
    g_warp[(size_t)(b*2  )*4096 + q] = sX*inv;
    g_warp[(size_t)(b*2+1)*4096 + q] = sY*inv;
}

// ---------------- coarse concat + grid_sample (zero padding) ----------------
__global__ void pack_coarse(const float* __restrict__ f0c, const float* __restrict__ f1c)
{
    int i = blockIdx.x*256 + threadIdx.x;      // 16384
    if (i >= 16384) return;
    int b = i>>12, p = i&4095;
    float wx = g_warp[(size_t)(b*2  )*4096 + p];
    float wy = g_warp[(size_t)(b*2+1)*4096 + p];
    float* xb = g_cat + (size_t)b*136*4096;
    if (blockIdx.y == 0) {
        xb[(size_t)128*4096 + p] = wx;
        xb[(size_t)129*4096 + p] = wy;
#pragma unroll
        for (int c=130;c<136;c++) xb[(size_t)c*4096 + p] = 0.f;
    }

    float fx = (wx + 1.f)*32.f - 0.5f;
    float fy = (wy + 1.f)*32.f - 0.5f;
    float flx = floorf(fx), fly = floorf(fy);
    float ax = fx - flx, ay = fy - fly;
    int xi = (int)flx, yi = (int)fly;
    float vx0 = ((unsigned)xi     < 64u) ? 1.f : 0.f;
    float vx1 = ((unsigned)(xi+1) < 64u) ? 1.f : 0.f;
    float vy0 = ((unsigned)yi     < 64u) ? 1.f : 0.f;
    float vy1 = ((unsigned)(yi+1) < 64u) ? 1.f : 0.f;
    int cx0 = min(max(xi,0),63),   cx1 = min(max(xi+1,0),63);
    int cy0 = min(max(yi,0),63),   cy1 = min(max(yi+1,0),63);
    float w00 = (1.f-ax)*(1.f-ay)*vx0*vy0;
    float w01 = ax*(1.f-ay)*vx1*vy0;
    float w10 = (1.f-ax)*ay*vx0*vy1;
    float w11 = ax*ay*vx1*vy1;
    const float* f1b = f1c + (size_t)b*262144;
    const float* f0b = f0c + (size_t)b*262144;
    int i00 = cy0*64+cx0, i01 = cy0*64+cx1, i10 = cy1*64+cx0, i11 = cy1*64+cx1;
    int cs = blockIdx.y*16;
    for (int c=cs;c<cs+16;c++) {
        const float* fc = f1b + (size_t)c*4096;
        float v = w00*fc[i00] + w01*fc[i01] + w10*fc[i10] + w11*fc[i11];
        xb[(size_t)(64+c)*4096 + p] = v;
        xb[(size_t)c*4096 + p]      = f0b[(size_t)c*4096 + p];
    }
}

// ---------------- direct 3x3 conv, SAME pad, no bias ----------------
// 32 oc x (8 rows x 32 cols). 256 thr, each 4 oc x 8 px as 4 f32x2 pairs.
// Warp: gy = lane>>2 (0..7), gx = (lane&3)*8. sIn row stride 35:
//   bank = 3*gy + gx + j (mod 32); 3*dgy+dgx ≡ 0 (mod 32) forces dgy ≡ 0 (mod 8)
//   -> scalar LDS conflict-free.
// Inner product uses packed fma.rn.f32x2 (2 FMA/instr) to beat the FFMA rt=2 ceiling.
// Double-buffered cp.async staging of input halo + weights.
template<int CINP>
__global__ void __launch_bounds__(256) conv3x3_kernel(
    const float* __restrict__ in, const float* __restrict__ wgt,
    float* __restrict__ out, int cinReal, int cout, int H, int W)
{
    __shared__ __align__(16) float sIn[2][8][10][35];
    __shared__ __align__(16) float sW[2][8][9][32];
    const int HW = H*W;
    const int tilesX = W >> 5;
    const int tx = blockIdx.x % tilesX;
    const int ty = blockIdx.x / tilesX;
    const int ocb = blockIdx.y << 5;
    const int b = blockIdx.z;
    const int tid = threadIdx.x;
    const int lane = tid & 31;
    const int wid = tid >> 5;
    const int gx = (lane & 3) << 3;   // x base: 0,8,16,24
    const int gy = lane >> 2;         // row 0..7
    const int ocl = wid << 2;         // local oc base 0..28
    const int x0 = tx << 5, y0 = ty << 3;
    const float* inB = in + (size_t)b*CINP*HW;
    constexpr int NCH = CINP/8;

    auto stage = [&](int buf, int c0) {
        for (int idx=tid; idx<2720; idx+=256) {
            int ic = idx/340;
            int rem = idx - ic*340;
            int r  = rem/34;
            int cl = rem - r*34;
            int yy = y0-1+r, xx = x0-1+cl;
            bool ok = ((unsigned)yy < (unsigned)H) && ((unsigned)xx < (unsigned)W);
            int yc = min(max(yy,0),H-1), xc = min(max(xx,0),W-1);
            const float* src = inB + (size_t)(c0+ic)*HW + yc*W + xc;
            cp_async4(smem_u32(&sIn[buf][ic][r][cl]), src, ok ? 4 : 0);
        }
        for (int idx=tid; idx<2304; idx+=256) {
            int ic = idx/288;
            int rem = idx - ic*288;
            int k  = rem >> 5;
            int o  = rem & 31;
            int icg = c0 + ic;
            int icc = min(icg, cinReal-1);
            const float* src = wgt + ((size_t)(ocb+o)*cinReal + icc)*9 + k;
            cp_async4(smem_u32(&sW[buf][ic][k][o]), src, (icg < cinReal) ? 4 : 0);
        }
        cp_commit();
    };

    ull acc2[4][4];
#pragma unroll
    for (int o=0;o<4;o++)
#pragma unroll
        for (int j=0;j<4;j++) acc2[o][j] = 0ull;

    stage(0, 0);

    for (int ci=0; ci<NCH; ci++) {
        if (ci+1 < NCH) {
            stage((ci+1)&1, (ci+1)*8);
            cp_wait1();
        } else {
            cp_wait0();
        }
        __syncthreads();
        const int buf = ci & 1;
#pragma unroll
        for (int ic=0;ic<8;ic++) {
#pragma unroll
            for (int kh=0;kh<3;kh++) {
                float r[10];
#pragma unroll
                for (int j=0;j<10;j++) r[j] = sIn[buf][ic][gy+kh][gx+j];
                ull pe[5], po[4];
#pragma unroll
                for (int j=0;j<5;j++) pe[j] = pk2(r[2*j], r[2*j+1]);
#pragma unroll
                for (int j=0;j<4;j++) po[j] = pk2(r[2*j+1], r[2*j+2]);
#pragma unroll
                for (int kw=0;kw<3;kw++) {
                    float4 w4 = *(const float4*)&sW[buf][ic][kh*3+kw][ocl];
                    ull wq0 = pk2(w4.x, w4.x);
                    ull wq1 = pk2(w4.y, w4.y);
                    ull wq2 = pk2(w4.z, w4.z);
                    ull wq3 = pk2(w4.w, w4.w);
                    const ull* sp = (kw==0) ? pe : (kw==1) ? po : (pe+1);
#pragma unroll
                    for (int j=0;j<4;j++) {
                        fma2(acc2[0][j], wq0, sp[j]);
                        fma2(acc2[1][j], wq1, sp[j]);
                        fma2(acc2[2][j], wq2, sp[j]);
                        fma2(acc2[3][j], wq3, sp[j]);
                    }
                }
            }
        }
        __syncthreads();
    }
#pragma unroll
    for (int o=0;o<4;o++) {
        float a0,a1,a2,a3,a4,a5,a6,a7;
        unpk2(acc2[o][0], a0, a1);
        unpk2(acc2[o][1], a2, a3);
        unpk2(acc2[o][2], a4, a5);
        unpk2(acc2[o][3], a6, a7);
        float* op = &out[((size_t)b*cout + (ocb+ocl+o))*HW + (y0+gy)*W + x0+gx];
        *(float4*)op       = make_float4(a0,a1,a2,a3);
        *(float4*)(op + 4) = make_float4(a4,a5,a6,a7);
    }
}

// ---------------- batch-norm: per-channel stats over (B,H,W) ----------------
__global__ void bn_reduce(const float* __restrict__ x, int C, int HW)
{
    const int c = blockIdx.x;
    const int tid = threadIdx.x;
    const int HW4 = HW >> 2;
    float s = 0.f, s2 = 0.f;
    for (int b=0;b<4;b++) {
        const float4* xb = (const float4*)(x + ((size_t)b*C + c)*HW);
        for (int p=tid; p<HW4; p+=256) {
            float4 v = xb[p];
            s  += v.x + v.y + v.z + v.w;
            s2 += v.x*v.x + v.y*v.y + v.z*v.z + v.w*v.w;
        }
    }
    __shared__ float rs[256];
    __shared__ float rq[256];
    rs[tid] = s; rq[tid] = s2;
    __syncthreads();
    for (int off=128; off>0; off>>=1) {
        if (tid < off) { rs[tid]+=rs[tid+off]; rq[tid]+=rq[tid+off]; }
        __syncthreads();
    }
    if (tid == 0) {
        float invN = 1.0f/(4.0f*HW);
        float m = rs[0]*invN;
        float var = rq[0]*invN - m*m;
        g_mean[c] = m;
        g_istd[c] = rsqrtf(var + 1e-5f);
    }
}

// in-place BN + ReLU, float4 vectorized (HW multiple of 4)
__global__ void bn_apply(float* __restrict__ x, int cMask, int hwShift)
{
    int idx = blockIdx.x*256 + threadIdx.x;   // element/4 index
    int c = (idx >> (hwShift-2)) & cMask;
    float m = g_mean[c], is = g_istd[c];
    float4 v = ((float4*)x)[idx];
    v.x = fmaxf((v.x - m)*is, 0.f);
    v.y = fmaxf((v.y - m)*is, 0.f);
    v.z = fmaxf((v.z - m)*is, 0.f);
    v.w = fmaxf((v.w - m)*is, 0.f);
    ((float4*)x)[idx] = v;
}

// ---------------- heads (1x1 conv + bias + residual) ----------------
__global__ void head_coarse(const float* __restrict__ w, const float* __restrict__ bias,
                            float* __restrict__ out)
{
    __shared__ float sw[768];
    for (int idx=threadIdx.x; idx<768; idx+=256) sw[idx] = w[idx];
    __syncthreads();
    int i = blockIdx.x*256 + threadIdx.x;     // 16384
    int b = i>>12, p = i&4095;
    const float* xb = g_bufB + (size_t)b*256*4096 + p;
    float a0 = bias[0], a1 = bias[1], a2 = bias[2];
    for (int c=0;c<256;c++) {
        float v = xb[(size_t)c*4096];
        a0 = fmaf(v, sw[c],     a0);
        a1 = fmaf(v, sw[256+c], a1);
        a2 = fmaf(v, sw[512+c], a2);
    }
    out[(size_t)(b*3  )*4096 + p] = g_warp[(size_t)(b*2  )*4096 + p] + a0;
    out[(size_t)(b*3+1)*4096 + p] = g_warp[(size_t)(b*2+1)*4096 + p] + a1;
    out[(size_t)(b*3+2)*4096 + p] = a2;
}

// ---------------- 2x bilinear upsample (half-pixel, edge-clamped) ----------------
__global__ void upsample_kernel(const float* __restrict__ cm)
{
    int idx = blockIdx.x*256 + threadIdx.x;   // 196608
    if (idx >= 196608) return;
    int p  = idx & 16383;
    int bc = idx >> 14;
    int ox = p & 127, oy = p >> 7;
    float sx = 0.5f*ox - 0.25f;
    float sy = 0.5f*oy - 0.25f;
    float fx = floorf(sx), fy = floorf(sy);
    float ax = sx - fx, ay = sy - fy;
    int x0 = (int)fx, y0 = (int)fy;
    int x0c = max(x0,0), x1c = min(x0+1,63);
    int y0c = max(y0,0), y1c = min(y0+1,63);
    const float* inb = cm + (size_t)bc*4096;
    float v00 = inb[y0c*64+x0c], v01 = inb[y0c*64+x1c];
    float v10 = inb[y1c*64+x0c], v11 = inb[y1c*64+x1c];
    g_up[idx] = (1.f-ay)*((1.f-ax)*v00 + ax*v01) + ay*((1.f-ax)*v10 + ax*v11);
}

// ---------------- fine concat + grid_sample ----------------
__global__ void pack_fine(const float* __restrict__ f0f, const float* __restrict__ f1f)
{
    int i = blockIdx.x*256 + threadIdx.x;     // 65536
    if (i >= 65536) return;
    int b = i>>14, p = i&16383;
    float wx = g_up[(size_t)(b*3  )*16384 + p];
    float wy = g_up[(size_t)(b*3+1)*16384 + p];
    float* yb = g_cat + (size_t)b*56*16384;
    if (blockIdx.y == 0) {
        yb[(size_t)48*16384 + p] = wx;
        yb[(size_t)49*16384 + p] = wy;
#pragma unroll
        for (int c=50;c<56;c++) yb[(size_t)c*16384 + p] = 0.f;
    }

    float fx = (wx + 1.f)*64.f - 0.5f;
    float fy = (wy + 1.f)*64.f - 0.5f;
    float flx = floorf(fx), fly = floorf(fy);
    float ax = fx - flx, ay = fy - fly;
    int xi = (int)flx, yi = (int)fly;
    float vx0 = ((unsigned)xi     < 128u) ? 1.f : 0.f;
    float vx1 = ((unsigned)(xi+1) < 128u) ? 1.f : 0.f;
    float vy0 = ((unsigned)yi     < 128u) ? 1.f : 0.f;
    float vy1 = ((unsigned)(yi+1) < 128u) ? 1.f : 0.f;
    int cx0 = min(max(xi,0),127),  cx1 = min(max(xi+1,0),127);
    int cy0 = min(max(yi,0),127),  cy1 = min(max(yi+1,0),127);
    float w00 = (1.f-ax)*(1.f-ay)*vx0*vy0;
    float w01 = ax*(1.f-ay)*vx1*vy0;
    float w10 = (1.f-ax)*ay*vx0*vy1;
    float w11 = ax*ay*vx1*vy1;
    const float* f1b = f1f + (size_t)b*24*16384;
    const float* f0b = f0f + (size_t)b*24*16384;
    int i00 = cy0*128+cx0, i01 = cy0*128+cx1, i10 = cy1*128+cx0, i11 = cy1*128+cx1;
    int cs = blockIdx.y*6;
    for (int c=cs;c<cs+6;c++) {
        const float* fc = f1b + (size_t)c*16384;
        float v = w00*fc[i00] + w01*fc[i01] + w10*fc[i10] + w11*fc[i11];
        yb[(size_t)(24+c)*16384 + p] = v;
        yb[(size_t)c*16384 + p]      = f0b[(size_t)c*16384 + p];
    }
}

__global__ void head_fine(const float* __restrict__ w, const float* __restrict__ bias,
                          float* __restrict__ out)
{
    __shared__ float sw[192];
    for (int idx=threadIdx.x; idx<192; idx+=256) sw[idx] = w[idx];
    __syncthreads();
    int i = blockIdx.x*256 + threadIdx.x;     // 65536
    int b = i>>14, p = i&16383;
    const float* yb = g_bufB + (size_t)b*64*16384 + p;
    float a0 = bias[0], a1 = bias[1], a2 = bias[2];
    for (int c=0;c<64;c++) {
        float v = yb[(size_t)c*16384];
        a0 = fmaf(v, sw[c],      a0);
        a1 = fmaf(v, sw[64+c],   a1);
        a2 = fmaf(v, sw[128+c],  a2);
    }
    out[(size_t)(b*3  )*16384 + p] = g_up[(size_t)(b*3  )*16384 + p] + a0;
    out[(size_t)(b*3+1)*16384 + p] = g_up[(size_t)(b*3+1)*16384 + p] + a1;
    out[(size_t)(b*3+2)*16384 + p] = g_up[(size_t)(b*3+2)*16384 + p] + a2;
}

// ---------------- launch ----------------
extern "C" void kernel_launch(void* const* d_in, const int* in_sizes, int n_in,
                              void* d_out, int out_size)
{
    const float* f0c = (const float*)d_in[0];
    const float* f1c = (const float*)d_in[1];
    const float* f0f = (const float*)d_in[2];
    const float* f1f = (const float*)d_in[3];
    const float* cw1 = (const float*)d_in[4];
    const float* cw2 = (const float*)d_in[5];
    const float* cw3 = (const float*)d_in[6];
    const float* cw4 = (const float*)d_in[7];
    const float* cw5 = (const float*)d_in[8];
    const float* cb5 = (const float*)d_in[9];
    const float* fw1 = (const float*)d_in[10];
    const float* fw2 = (const float*)d_in[11];
    const float* fw3 = (const float*)d_in[12];
    const float* fw4 = (const float*)d_in[13];
    const float* fw5 = (const float*)d_in[14];
    const float* fb5 = (const float*)d_in[15];

    float *pCat, *pA, *pB;
    cudaGetSymbolAddress((void**)&pCat, g_cat);
    cudaGetSymbolAddress((void**)&pA,   g_bufA);
    cudaGetSymbolAddress((void**)&pB,   g_bufB);

    float* outC = (float*)d_out;          // (4,3,64,64)
    float* outF = outC + 49152;           // (4,3,128,128)

    // coarse attention -> warp field
    attn_kernel<<<dim3(16,4,4),256>>>(f0c, f1c);
    attn_combine<<<64,256>>>();
    pack_coarse<<<dim3(64,4),256>>>(f0c, f1c);

    // coarse conv tower: conv -> stats -> in-place BN+ReLU
    // conv grid: (tilesX*tilesY, cout/32, B) = (2*8, 8, 4) = 512 blocks
    conv3x3_kernel<136><<<dim3(16,8,4),256>>>(pCat, cw1, pA, 130, 256, 64, 64);
    bn_reduce<<<256,256>>>(pA, 256, 4096);
    bn_apply<<<4096,256>>>(pA, 255, 12);
    conv3x3_kernel<256><<<dim3(16,8,4),256>>>(pA, cw2, pB, 256, 256, 64, 64);
    bn_reduce<<<256,256>>>(pB, 256, 4096);
    bn_apply<<<4096,256>>>(pB, 255, 12);
    conv3x3_kernel<256><<<dim3(16,8,4),256>>>(pB, cw3, pA, 256, 256, 64, 64);
    bn_reduce<<<256,256>>>(pA, 256, 4096);
    bn_apply<<<4096,256>>>(pA, 255, 12);
    conv3x3_kernel<256><<<dim3(16,8,4),256>>>(pA, cw4, pB, 256, 256, 64, 64);
    bn_reduce<<<256,256>>>(pB, 256, 4096);
    bn_apply<<<4096,256>>>(pB, 255, 12);

    head_coarse<<<64,256>>>(cw5, cb5, outC);

    // fine stage
    upsample_kernel<<<768,256>>>(outC);
    pack_fine<<<dim3(256,4),256>>>(f0f, f1f);

    // fine conv grid: (4*16, 2, 4) = 512 blocks
    conv3x3_kernel<56><<<dim3(64,2,4),256>>>(pCat, fw1, pA, 50, 64, 128, 128);
    bn_reduce<<<64,256>>>(pA, 64, 16384);
    bn_apply<<<4096,256>>>(pA, 63, 14);
    conv3x3_kernel<64><<<dim3(64,2,4),256>>>(pA, fw2, pB, 64, 64, 128, 128);
    bn_reduce<<<64,256>>>(pB, 64, 16384);
    bn_apply<<<4096,256>>>(pB, 63, 14);
    conv3x3_kernel<64><<<dim3(64,2,4),256>>>(pB, fw3, pA, 64, 64, 128, 128);
    bn_reduce<<<64,256>>>(pA, 64, 16384);
    bn_apply<<<4096,256>>>(pA, 63, 14);
    conv3x3_kernel<64><<<dim3(64,2,4),256>>>(pA, fw4, pB, 64, 64, 128, 128);
    bn_reduce<<<64,256>>>(pB, 64, 16384);
    bn_apply<<<4096,256>>>(pB, 63, 14);

    head_fine<<<256,256>>>(fw5, fb5, outF);
}

// round 11
// speedup vs baseline: 1.3351x; 1.0941x over previous
#include <cuda_runtime.h>
#include <cstdint>
#include <math.h>

// ---------------- scratch (static __device__, no allocation) ----------------
__device__ float g_part[4*4*3*4096];     // attention partials [b][ks][3][q]
__device__ float g_warp[4*2*4096];       // coarse_warp [b][2][p]
__device__ float g_cat[3670016];         // concat input: coarse 4*136*4096 / fine 4*56*16384
__device__ float g_bufA[4194304];        // conv ping
__device__ float g_bufB[4194304];        // conv pong
__device__ float g_up[4*3*16384];        // upsampled coarse matches
__device__ float g_mean[256];
__device__ float g_istd[256];

// ---------------- cp.async helpers ----------------
__device__ __forceinline__ uint32_t smem_u32(const void* p) {
    return (uint32_t)__cvta_generic_to_shared(p);
}
__device__ __forceinline__ void cp_async4(uint32_t dst, const void* src, int srcsz) {
    asm volatile("cp.async.ca.shared.global [%0], [%1], 4, %2;\n"
                 :: "r"(dst), "l"(src), "r"(srcsz));
}
__device__ __forceinline__ void cp_commit() {
    asm volatile("cp.async.commit_group;\n");
}
__device__ __forceinline__ void cp_wait1() {
    asm volatile("cp.async.wait_group 1;\n");
}
__device__ __forceinline__ void cp_wait0() {
    asm volatile("cp.async.wait_group 0;\n");
}

// ---------------- tf32 mma helpers ----------------
__device__ __forceinline__ void tf32split(float f, uint32_t& hi, uint32_t& lo) {
    asm("cvt.rna.tf32.f32 %0, %1;" : "=r"(hi) : "f"(f));
    lo = __float_as_uint(f - __uint_as_float(hi));   // HW truncates low bits
}
__device__ __forceinline__ void mma_tf32(float* c, const uint32_t* a, const uint32_t* b) {
    asm volatile("mma.sync.aligned.m16n8k8.row.col.f32.tf32.tf32.f32 "
        "{%0,%1,%2,%3}, {%4,%5,%6,%7}, {%8,%9}, {%0,%1,%2,%3};"
        : "+f"(c[0]), "+f"(c[1]), "+f"(c[2]), "+f"(c[3])
        : "r"(a[0]), "r"(a[1]), "r"(a[2]), "r"(a[3]), "r"(b[0]), "r"(b[1]));
}

// ---------------- fused correlation-softmax-expectation ----------------
__global__ void __launch_bounds__(256) attn_kernel(const float* __restrict__ f0,
                                                   const float* __restrict__ f1)
{
    __shared__ __align__(16) float sK[64][64];
    const int qb = blockIdx.x, ks = blockIdx.y, b = blockIdx.z;
    const int q = qb*256 + threadIdx.x;
    const float* f0b = f0 + (size_t)b*262144;
    const float* f1b = f1 + (size_t)b*262144;
    float qv[64];
#pragma unroll
    for (int c=0;c<64;c++) qv[c] = f0b[c*4096 + q];
    float sE=0.f, sX=0.f, sY=0.f;
    const int kbase = ks*1024;
    for (int t=0; t<1024; t+=64) {
        __syncthreads();
        const int k0 = kbase + t;
        for (int idx=threadIdx.x; idx<4096; idx+=256) {
            int c = idx>>6, kk = idx&63;
            sK[c][kk] = f1b[c*4096 + k0 + kk];
        }
        __syncthreads();
        const float gyv = (float)((k0>>6)*2 + 1)*0.015625f - 1.0f;
        for (int kk=0; kk<64; kk+=4) {
            float d0=0.f,d1=0.f,d2=0.f,d3=0.f;
#pragma unroll
            for (int c=0;c<64;c++) {
                float4 kv = *(const float4*)&sK[c][kk];
                d0 = fmaf(qv[c], kv.x, d0);
                d1 = fmaf(qv[c], kv.y, d1);
                d2 = fmaf(qv[c], kv.z, d2);
                d3 = fmaf(qv[c], kv.w, d3);
            }
            float e0 = __expf(d0*0.125f);
            float e1 = __expf(d1*0.125f);
            float e2 = __expf(d2*0.125f);
            float e3 = __expf(d3*0.125f);
            float gx0 = (float)((((k0+kk)&63)*2)+1)*0.015625f - 1.0f;
            float es = e0+e1+e2+e3;
            sE += es;
            sY = fmaf(es, gyv, sY);
            sX += e0*gx0 + e1*(gx0+0.03125f) + e2*(gx0+0.0625f) + e3*(gx0+0.09375f);
        }
    }
    size_t base = ((size_t)(b*4+ks)*3)*4096 + q;
    g_part[base        ] = sE;
    g_part[base +  4096] = sX;
    g_part[base +  8192] = sY;
}

__global__ void attn_combine()
{
    int i = blockIdx.x*256 + threadIdx.x;      // 16384
    if (i >= 16384) return;
    int b = i>>12, q = i&4095;
    float sE=0.f, sX=0.f, sY=0.f;
    for (int ks=0; ks<4; ks++) {
        size_t base = ((size_t)(b*4+ks)*3)*4096 + q;
        sE += g_part[base];
        sX += g_part[base+4096];
        sY += g_part[base+8192];
    }
    float inv = 1.0f/sE;
    g_warp[(size_t)(b*2  )*4096 + q] = sX*inv;
    g_warp[(size_t)(b*2+1)*4096 + q] = sY*inv;
}

// ---------------- coarse concat + grid_sample (zero padding) ----------------
__global__ void pack_coarse(const float* __restrict__ f0c, const float* __restrict__ f1c)
{
    int i = blockIdx.x*256 + threadIdx.x;      // 16384
    if (i >= 16384) return;
    int b = i>>12, p = i&4095;
    float wx = g_warp[(size_t)(b*2  )*4096 + p];
    float wy = g_warp[(size_t)(b*2+1)*4096 + p];
    float* xb = g_cat + (size_t)b*136*4096;
    if (blockIdx.y == 0) {
        xb[(size_t)128*4096 + p] = wx;
        xb[(size_t)129*4096 + p] = wy;
#pragma unroll
        for (int c=130;c<136;c++) xb[(size_t)c*4096 + p] = 0.f;
    }

    float fx = (wx + 1.f)*32.f - 0.5f;
    float fy = (wy + 1.f)*32.f - 0.5f;
    float flx = floorf(fx), fly = floorf(fy);
    float ax = fx - flx, ay = fy - fly;
    int xi = (int)flx, yi = (int)fly;
    float vx0 = ((unsigned)xi     < 64u) ? 1.f : 0.f;
    float vx1 = ((unsigned)(xi+1) < 64u) ? 1.f : 0.f;
    float vy0 = ((unsigned)yi     < 64u) ? 1.f : 0.f;
    float vy1 = ((unsigned)(yi+1) < 64u) ? 1.f : 0.f;
    int cx0 = min(max(xi,0),63),   cx1 = min(max(xi+1,0),63);
    int cy0 = min(max(yi,0),63),   cy1 = min(max(yi+1,0),63);
    float w00 = (1.f-ax)*(1.f-ay)*vx0*vy0;
    float w01 = ax*(1.f-ay)*vx1*vy0;
    float w10 = (1.f-ax)*ay*vx0*vy1;
    float w11 = ax*ay*vx1*vy1;
    const float* f1b = f1c + (size_t)b*262144;
    const float* f0b = f0c + (size_t)b*262144;
    int i00 = cy0*64+cx0, i01 = cy0*64+cx1, i10 = cy1*64+cx0, i11 = cy1*64+cx1;
    int cs = blockIdx.y*16;
    for (int c=cs;c<cs+16;c++) {
        const float* fc = f1b + (size_t)c*4096;
        float v = w00*fc[i00] + w01*fc[i01] + w10*fc[i10] + w11*fc[i11];
        xb[(size_t)(64+c)*4096 + p] = v;
        xb[(size_t)c*4096 + p]      = f0b[(size_t)c*4096 + p];
    }
}

// ---------------- tf32 tensor-core 3x3 conv, SAME pad, no bias ----------------
// Block: 32 oc x (8 rows x 32 cols). 8 warps; warp w owns output row w.
// Per warp: 2 M-tiles (16 px each) x 4 N-tiles (8 oc) of mma.m16n8k8 (K=8 ic),
// 3xTF32 precision split (hi/lo), fp32 accumulators.
// smem: sIn[r][x][ic pad 9] (frag LDS banks = 9g+t, near conflict-free),
//       sW[k][oc][ic pad 9]. Double-buffered cp.async.
template<int CINP>
__global__ void __launch_bounds__(256) conv3x3_mma(
    const float* __restrict__ in, const float* __restrict__ wgt,
    float* __restrict__ out, int cinReal, int cout, int H, int W)
{
    __shared__ __align__(16) float sIn[2][10][34][9];
    __shared__ __align__(16) float sW[2][9][32][9];
    const int HW = H*W;
    const int tilesX = W >> 5;
    const int tx = blockIdx.x % tilesX;
    const int ty = blockIdx.x / tilesX;
    const int ocb = blockIdx.y << 5;
    const int b = blockIdx.z;
    const int tid = threadIdx.x;
    const int lane = tid & 31;
    const int wid = tid >> 5;      // warp = output row 0..7
    const int g = lane >> 2;       // group 0..7
    const int t = lane & 3;        // thread-in-group 0..3
    const int x0 = tx << 5, y0 = ty << 3;
    const float* inB = in + (size_t)b*CINP*HW;
    constexpr int NCH = CINP/8;

    auto stage = [&](int buf, int c0) {
        for (int idx=tid; idx<2720; idx+=256) {
            int ic = idx/340;
            int rem = idx - ic*340;
            int r  = rem/34;
            int cl = rem - r*34;
            int yy = y0-1+r, xx = x0-1+cl;
            bool ok = ((unsigned)yy < (unsigned)H) && ((unsigned)xx < (unsigned)W);
            int yc = min(max(yy,0),H-1), xc = min(max(xx,0),W-1);
            const float* src = inB + (size_t)(c0+ic)*HW + yc*W + xc;
            cp_async4(smem_u32(&sIn[buf][r][cl][ic]), src, ok ? 4 : 0);
        }
        for (int idx=tid; idx<2304; idx+=256) {
            int ic = idx/288;
            int rem = idx - ic*288;
            int k  = rem >> 5;
            int o  = rem & 31;
            int icg = c0 + ic;
            int icc = min(icg, cinReal-1);
            const float* src = wgt + ((size_t)(ocb+o)*cinReal + icc)*9 + k;
            cp_async4(smem_u32(&sW[buf][k][o][ic]), src, (icg < cinReal) ? 4 : 0);
        }
        cp_commit();
    };

    float c[2][4][4];
#pragma unroll
    for (int m=0;m<2;m++)
#pragma unroll
        for (int n=0;n<4;n++)
#pragma unroll
            for (int e=0;e<4;e++) c[m][n][e] = 0.f;

    stage(0, 0);

    for (int ci=0; ci<NCH; ci++) {
        if (ci+1 < NCH) {
            stage((ci+1)&1, (ci+1)*8);
            cp_wait1();
        } else {
            cp_wait0();
        }
        __syncthreads();
        const int buf = ci & 1;
#pragma unroll
        for (int kh=0;kh<3;kh++) {
            const float* rowp = &sIn[buf][wid+kh][0][0];   // [34][9]
#pragma unroll
            for (int kw=0;kw<3;kw++) {
                uint32_t Ahi[2][4], Alo[2][4];
#pragma unroll
                for (int m=0;m<2;m++) {
                    int xb = 16*m + kw + g;
                    float f0 = rowp[xb*9 + t];
                    float f1 = rowp[(xb+8)*9 + t];
                    float f2 = rowp[xb*9 + t + 4];
                    float f3 = rowp[(xb+8)*9 + t + 4];
                    tf32split(f0, Ahi[m][0], Alo[m][0]);
                    tf32split(f1, Ahi[m][1], Alo[m][1]);
                    tf32split(f2, Ahi[m][2], Alo[m][2]);
                    tf32split(f3, Ahi[m][3], Alo[m][3]);
                }
                const float* wp = &sW[buf][kh*3+kw][0][0]; // [32][9]
                uint32_t Bhi[4][2], Blo[4][2];
#pragma unroll
                for (int n=0;n<4;n++) {
                    float h0 = wp[(8*n+g)*9 + t];
                    float h1 = wp[(8*n+g)*9 + t + 4];
                    tf32split(h0, Bhi[n][0], Blo[n][0]);
                    tf32split(h1, Bhi[n][1], Blo[n][1]);
                }
#pragma unroll
                for (int m=0;m<2;m++)
#pragma unroll
                    for (int n=0;n<4;n++) {
                        mma_tf32(c[m][n], Ahi[m], Bhi[n]);
                        mma_tf32(c[m][n], Ahi[m], Blo[n]);
                        mma_tf32(c[m][n], Alo[m], Bhi[n]);
                    }
            }
        }
        __syncthreads();
    }

    const int oy = y0 + wid;
#pragma unroll
    for (int m=0;m<2;m++) {
#pragma unroll
        for (int n=0;n<4;n++) {
            int oc = ocb + 8*n + 2*t;
            float* p0 = out + ((size_t)b*cout + oc)*HW + oy*W + x0 + 16*m + g;
            p0[0] = c[m][n][0];
            p0[8] = c[m][n][2];
            float* p1 = p0 + HW;
            p1[0] = c[m][n][1];
            p1[8] = c[m][n][3];
        }
    }
}

// ---------------- batch-norm: per-channel stats over (B,H,W) ----------------
__global__ void bn_reduce(const float* __restrict__ x, int C, int HW)
{
    const int c = blockIdx.x;
    const int tid = threadIdx.x;
    const int HW4 = HW >> 2;
    float s = 0.f, s2 = 0.f;
    for (int b=0;b<4;b++) {
        const float4* xb = (const float4*)(x + ((size_t)b*C + c)*HW);
        for (int p=tid; p<HW4; p+=256) {
            float4 v = xb[p];
            s  += v.x + v.y + v.z + v.w;
            s2 += v.x*v.x + v.y*v.y + v.z*v.z + v.w*v.w;
        }
    }
    __shared__ float rs[256];
    __shared__ float rq[256];
    rs[tid] = s; rq[tid] = s2;
    __syncthreads();
    for (int off=128; off>0; off>>=1) {
        if (tid < off) { rs[tid]+=rs[tid+off]; rq[tid]+=rq[tid+off]; }
        __syncthreads();
    }
    if (tid == 0) {
        float invN = 1.0f/(4.0f*HW);
        float m = rs[0]*invN;
        float var = rq[0]*invN - m*m;
        g_mean[c] = m;
        g_istd[c] = rsqrtf(var + 1e-5f);
    }
}

// in-place BN + ReLU, float4 vectorized (HW multiple of 4)
__global__ void bn_apply(float* __restrict__ x, int cMask, int hwShift)
{
    int idx = blockIdx.x*256 + threadIdx.x;   // element/4 index
    int c = (idx >> (hwShift-2)) & cMask;
    float m = g_mean[c], is = g_istd[c];
    float4 v = ((float4*)x)[idx];
    v.x = fmaxf((v.x - m)*is, 0.f);
    v.y = fmaxf((v.y - m)*is, 0.f);
    v.z = fmaxf((v.z - m)*is, 0.f);
    v.w = fmaxf((v.w - m)*is, 0.f);
    ((float4*)x)[idx] = v;
}

// ---------------- heads (1x1 conv + bias + residual) ----------------
__global__ void head_coarse(const float* __restrict__ w, const float* __restrict__ bias,
                            float* __restrict__ out)
{
    __shared__ float sw[768];
    for (int idx=threadIdx.x; idx<768; idx+=256) sw[idx] = w[idx];
    __syncthreads();
    int i = blockIdx.x*256 + threadIdx.x;     // 16384
    int b = i>>12, p = i&4095;
    const float* xb = g_bufB + (size_t)b*256*4096 + p;
    float a0 = bias[0], a1 = bias[1], a2 = bias[2];
    for (int c=0;c<256;c++) {
        float v = xb[(size_t)c*4096];
        a0 = fmaf(v, sw[c],     a0);
        a1 = fmaf(v, sw[256+c], a1);
        a2 = fmaf(v, sw[512+c], a2);
    }
    out[(size_t)(b*3  )*4096 + p] = g_warp[(size_t)(b*2  )*4096 + p] + a0;
    out[(size_t)(b*3+1)*4096 + p] = g_warp[(size_t)(b*2+1)*4096 + p] + a1;
    out[(size_t)(b*3+2)*4096 + p] = a2;
}

// ---------------- 2x bilinear upsample (half-pixel, edge-clamped) ----------------
__global__ void upsample_kernel(const float* __restrict__ cm)
{
    int idx = blockIdx.x*256 + threadIdx.x;   // 196608
    if (idx >= 196608) return;
    int p  = idx & 16383;
    int bc = idx >> 14;
    int ox = p & 127, oy = p >> 7;
    float sx = 0.5f*ox - 0.25f;
    float sy = 0.5f*oy - 0.25f;
    float fx = floorf(sx), fy = floorf(sy);
    float ax = sx - fx, ay = sy - fy;
    int x0 = (int)fx, y0 = (int)fy;
    int x0c = max(x0,0), x1c = min(x0+1,63);
    int y0c = max(y0,0), y1c = min(y0+1,63);
    const float* inb = cm + (size_t)bc*4096;
    float v00 = inb[y0c*64+x0c], v01 = inb[y0c*64+x1c];
    float v10 = inb[y1c*64+x0c], v11 = inb[y1c*64+x1c];
    g_up[idx] = (1.f-ay)*((1.f-ax)*v00 + ax*v01) + ay*((1.f-ax)*v10 + ax*v11);
}

// ---------------- fine concat + grid_sample ----------------
__global__ void pack_fine(const float* __restrict__ f0f, const float* __restrict__ f1f)
{
    int i = blockIdx.x*256 + threadIdx.x;     // 65536
    if (i >= 65536) return;
    int b = i>>14, p = i&16383;
    float wx = g_up[(size_t)(b*3  )*16384 + p];
    float wy = g_up[(size_t)(b*3+1)*16384 + p];
    float* yb = g_cat + (size_t)b*56*16384;
    if (blockIdx.y == 0) {
        yb[(size_t)48*16384 + p] = wx;
        yb[(size_t)49*16384 + p] = wy;
#pragma unroll
        for (int c=50;c<56;c++) yb[(size_t)c*16384 + p] = 0.f;
    }

    float fx = (wx + 1.f)*64.f - 0.5f;
    float fy = (wy + 1.f)*64.f - 0.5f;
    float flx = floorf(fx), fly = floorf(fy);
    float ax = fx - flx, ay = fy - fly;
    int xi = (int)flx, yi = (int)fly;
    float vx0 = ((unsigned)xi     < 128u) ? 1.f : 0.f;
    float vx1 = ((unsigned)(xi+1) < 128u) ? 1.f : 0.f;
    float vy0 = ((unsigned)yi     < 128u) ? 1.f : 0.f;
    float vy1 = ((unsigned)(yi+1) < 128u) ? 1.f : 0.f;
    int cx0 = min(max(xi,0),127),  cx1 = min(max(xi+1,0),127);
    int cy0 = min(max(yi,0),127),  cy1 = min(max(yi+1,0),127);
    float w00 = (1.f-ax)*(1.f-ay)*vx0*vy0;
    float w01 = ax*(1.f-ay)*vx1*vy0;
    float w10 = (1.f-ax)*ay*vx0*vy1;
    float w11 = ax*ay*vx1*vy1;
    const float* f1b = f1f + (size_t)b*24*16384;
    const float* f0b = f0f + (size_t)b*24*16384;
    int i00 = cy0*128+cx0, i01 = cy0*128+cx1, i10 = cy1*128+cx0, i11 = cy1*128+cx1;
    int cs = blockIdx.y*6;
    for (int c=cs;c<cs+6;c++) {
        const float* fc = f1b + (size_t)c*16384;
        float v = w00*fc[i00] + w01*fc[i01] + w10*fc[i10] + w11*fc[i11];
        yb[(size_t)(24+c)*16384 + p] = v;
        yb[(size_t)c*16384 + p]      = f0b[(size_t)c*16384 + p];
    }
}

__global__ void head_fine(const float* __restrict__ w, const float* __restrict__ bias,
                          float* __restrict__ out)
{
    __shared__ float sw[192];
    for (int idx=threadIdx.x; idx<192; idx+=256) sw[idx] = w[idx];
    __syncthreads();
    int i = blockIdx.x*256 + threadIdx.x;     // 65536
    int b = i>>14, p = i&16383;
    const float* yb = g_bufB + (size_t)b*64*16384 + p;
    float a0 = bias[0], a1 = bias[1], a2 = bias[2];
    for (int c=0;c<64;c++) {
        float v = yb[(size_t)c*16384];
        a0 = fmaf(v, sw[c],      a0);
        a1 = fmaf(v, sw[64+c],   a1);
        a2 = fmaf(v, sw[128+c],  a2);
    }
    out[(size_t)(b*3  )*16384 + p] = g_up[(size_t)(b*3  )*16384 + p] + a0;
    out[(size_t)(b*3+1)*16384 + p] = g_up[(size_t)(b*3+1)*16384 + p] + a1;
    out[(size_t)(b*3+2)*16384 + p] = g_up[(size_t)(b*3+2)*16384 + p] + a2;
}

// ---------------- launch ----------------
extern "C" void kernel_launch(void* const* d_in, const int* in_sizes, int n_in,
                              void* d_out, int out_size)
{
    const float* f0c = (const float*)d_in[0];
    const float* f1c = (const float*)d_in[1];
    const float* f0f = (const float*)d_in[2];
    const float* f1f = (const float*)d_in[3];
    const float* cw1 = (const float*)d_in[4];
    const float* cw2 = (const float*)d_in[5];
    const float* cw3 = (const float*)d_in[6];
    const float* cw4 = (const float*)d_in[7];
    const float* cw5 = (const float*)d_in[8];
    const float* cb5 = (const float*)d_in[9];
    const float* fw1 = (const float*)d_in[10];
    const float* fw2 = (const float*)d_in[11];
    const float* fw3 = (const float*)d_in[12];
    const float* fw4 = (const float*)d_in[13];
    const float* fw5 = (const float*)d_in[14];
    const float* fb5 = (const float*)d_in[15];

    float *pCat, *pA, *pB;
    cudaGetSymbolAddress((void**)&pCat, g_cat);
    cudaGetSymbolAddress((void**)&pA,   g_bufA);
    cudaGetSymbolAddress((void**)&pB,   g_bufB);

    float* outC = (float*)d_out;          // (4,3,64,64)
    float* outF = outC + 49152;           // (4,3,128,128)

    // coarse attention -> warp field
    attn_kernel<<<dim3(16,4,4),256>>>(f0c, f1c);
    attn_combine<<<64,256>>>();
    pack_coarse<<<dim3(64,4),256>>>(f0c, f1c);

    // coarse conv tower: conv -> stats -> in-place BN+ReLU
    // conv grid: (tilesX*tilesY, cout/32, B) = (2*8, 8, 4) = 512 blocks
    conv3x3_mma<136><<<dim3(16,8,4),256>>>(pCat, cw1, pA, 130, 256, 64, 64);
    bn_reduce<<<256,256>>>(pA, 256, 4096);
    bn_apply<<<4096,256>>>(pA, 255, 12);
    conv3x3_mma<256><<<dim3(16,8,4),256>>>(pA, cw2, pB, 256, 256, 64, 64);
    bn_reduce<<<256,256>>>(pB, 256, 4096);
    bn_apply<<<4096,256>>>(pB, 255, 12);
    conv3x3_mma<256><<<dim3(16,8,4),256>>>(pB, cw3, pA, 256, 256, 64, 64);
    bn_reduce<<<256,256>>>(pA, 256, 4096);
    bn_apply<<<4096,256>>>(pA, 255, 12);
    conv3x3_mma<256><<<dim3(16,8,4),256>>>(pA, cw4, pB, 256, 256, 64, 64);
    bn_reduce<<<256,256>>>(pB, 256, 4096);
    bn_apply<<<4096,256>>>(pB, 255, 12);

    head_coarse<<<64,256>>>(cw5, cb5, outC);

    // fine stage
    upsample_kernel<<<768,256>>>(outC);
    pack_fine<<<dim3(256,4),256>>>(f0f, f1f);

    // fine conv grid: (4*16, 2, 4) = 512 blocks
    conv3x3_mma<56><<<dim3(64,2,4),256>>>(pCat, fw1, pA, 50, 64, 128, 128);
    bn_reduce<<<64,256>>>(pA, 64, 16384);
    bn_apply<<<4096,256>>>(pA, 63, 14);
    conv3x3_mma<64><<<dim3(64,2,4),256>>>(pA, fw2, pB, 64, 64, 128, 128);
    bn_reduce<<<64,256>>>(pB, 64, 16384);
    bn_apply<<<4096,256>>>(pB, 63, 14);
    conv3x3_mma<64><<<dim3(64,2,4),256>>>(pB, fw3, pA, 64, 64, 128, 128);
    bn_reduce<<<64,256>>>(pA, 64, 16384);
    bn_apply<<<4096,256>>>(pA, 63, 14);
    conv3x3_mma<64><<<dim3(64,2,4),256>>>(pA, fw4, pB, 64, 64, 128, 128);
    bn_reduce<<<64,256>>>(pB, 64, 16384);
    bn_apply<<<4096,256>>>(pB, 63, 14);

    head_fine<<<256,256>>>(fw5, fb5, outF);
}

// round 12
// speedup vs baseline: 1.5285x; 1.1449x over previous
#include <cuda_runtime.h>
#include <cstdint>
#include <math.h>

// ---------------- scratch (static __device__, no allocation) ----------------
__device__ float g_part[4*4*3*4096];     // attention partials [b][ks][3][q]
__device__ float g_warp[4*2*4096];       // coarse_warp [b][2][p]
__device__ float g_cat[3670016];         // concat input: coarse 4*136*4096 / fine 4*56*16384
__device__ float g_bufA[4194304];        // conv ping
__device__ float g_bufB[4194304];        // conv pong
__device__ float g_up[4*3*16384];        // upsampled coarse matches
__device__ float g_mean[256];
__device__ float g_istd[256];

// ---------------- cp.async helpers ----------------
__device__ __forceinline__ uint32_t smem_u32(const void* p) {
    return (uint32_t)__cvta_generic_to_shared(p);
}
__device__ __forceinline__ void cp_async4(uint32_t dst, const void* src, int srcsz) {
    asm volatile("cp.async.ca.shared.global [%0], [%1], 4, %2;\n"
                 :: "r"(dst), "l"(src), "r"(srcsz));
}
__device__ __forceinline__ void cp_commit() {
    asm volatile("cp.async.commit_group;\n");
}
__device__ __forceinline__ void cp_wait1() {
    asm volatile("cp.async.wait_group 1;\n");
}
__device__ __forceinline__ void cp_wait0() {
    asm volatile("cp.async.wait_group 0;\n");
}

// ---------------- tf32 mma helpers ----------------
__device__ __forceinline__ void tf32split(float f, uint32_t& hi, uint32_t& lo) {
    asm("cvt.rna.tf32.f32 %0, %1;" : "=r"(hi) : "f"(f));
    lo = __float_as_uint(f - __uint_as_float(hi));   // exact (Sterbenz)
}
__device__ __forceinline__ void mma_tf32(float* c, const uint32_t* a, const uint32_t* b) {
    asm volatile("mma.sync.aligned.m16n8k8.row.col.f32.tf32.tf32.f32 "
        "{%0,%1,%2,%3}, {%4,%5,%6,%7}, {%8,%9}, {%0,%1,%2,%3};"
        : "+f"(c[0]), "+f"(c[1]), "+f"(c[2]), "+f"(c[3])
        : "r"(a[0]), "r"(a[1]), "r"(a[2]), "r"(a[3]), "r"(b[0]), "r"(b[1]));
}

// ---------------- fused correlation-softmax-expectation ----------------
__global__ void __launch_bounds__(256) attn_kernel(const float* __restrict__ f0,
                                                   const float* __restrict__ f1)
{
    __shared__ __align__(16) float sK[64][64];
    const int qb = blockIdx.x, ks = blockIdx.y, b = blockIdx.z;
    const int q = qb*256 + threadIdx.x;
    const float* f0b = f0 + (size_t)b*262144;
    const float* f1b = f1 + (size_t)b*262144;
    float qv[64];
#pragma unroll
    for (int c=0;c<64;c++) qv[c] = f0b[c*4096 + q];
    float sE=0.f, sX=0.f, sY=0.f;
    const int kbase = ks*1024;
    for (int t=0; t<1024; t+=64) {
        __syncthreads();
        const int k0 = kbase + t;
        for (int idx=threadIdx.x; idx<4096; idx+=256) {
            int c = idx>>6, kk = idx&63;
            sK[c][kk] = f1b[c*4096 + k0 + kk];
        }
        __syncthreads();
        const float gyv = (float)((k0>>6)*2 + 1)*0.015625f - 1.0f;
        for (int kk=0; kk<64; kk+=4) {
            float d0=0.f,d1=0.f,d2=0.f,d3=0.f;
#pragma unroll
            for (int c=0;c<64;c++) {
                float4 kv = *(const float4*)&sK[c][kk];
                d0 = fmaf(qv[c], kv.x, d0);
                d1 = fmaf(qv[c], kv.y, d1);
                d2 = fmaf(qv[c], kv.z, d2);
                d3 = fmaf(qv[c], kv.w, d3);
            }
            float e0 = __expf(d0*0.125f);
            float e1 = __expf(d1*0.125f);
            float e2 = __expf(d2*0.125f);
            float e3 = __expf(d3*0.125f);
            float gx0 = (float)((((k0+kk)&63)*2)+1)*0.015625f - 1.0f;
            float es = e0+e1+e2+e3;
            sE += es;
            sY = fmaf(es, gyv, sY);
            sX += e0*gx0 + e1*(gx0+0.03125f) + e2*(gx0+0.0625f) + e3*(gx0+0.09375f);
        }
    }
    size_t base = ((size_t)(b*4+ks)*3)*4096 + q;
    g_part[base        ] = sE;
    g_part[base +  4096] = sX;
    g_part[base +  8192] = sY;
}

__global__ void attn_combine()
{
    int i = blockIdx.x*256 + threadIdx.x;      // 16384
    if (i >= 16384) return;
    int b = i>>12, q = i&4095;
    float sE=0.f, sX=0.f, sY=0.f;
    for (int ks=0; ks<4; ks++) {
        size_t base = ((size_t)(b*4+ks)*3)*4096 + q;
        sE += g_part[base];
        sX += g_part[base+4096];
        sY += g_part[base+8192];
    }
    float inv = 1.0f/sE;
    g_warp[(size_t)(b*2  )*4096 + q] = sX*inv;
    g_warp[(size_t)(b*2+1)*4096 + q] = sY*inv;
}

// ---------------- coarse concat + grid_sample (zero padding) ----------------
__global__ void pack_coarse(const float* __restrict__ f0c, const float* __restrict__ f1c)
{
    int i = blockIdx.x*256 + threadIdx.x;      // 16384
    if (i >= 16384) return;
    int b = i>>12, p = i&4095;
    float wx = g_warp[(size_t)(b*2  )*4096 + p];
    float wy = g_warp[(size_t)(b*2+1)*4096 + p];
    float* xb = g_cat + (size_t)b*136*4096;
    if (blockIdx.y == 0) {
        xb[(size_t)128*4096 + p] = wx;
        xb[(size_t)129*4096 + p] = wy;
#pragma unroll
        for (int c=130;c<136;c++) xb[(size_t)c*4096 + p] = 0.f;
    }

    float fx = (wx + 1.f)*32.f - 0.5f;
    float fy = (wy + 1.f)*32.f - 0.5f;
    float flx = floorf(fx), fly = floorf(fy);
    float ax = fx - flx, ay = fy - fly;
    int xi = (int)flx, yi = (int)fly;
    float vx0 = ((unsigned)xi     < 64u) ? 1.f : 0.f;
    float vx1 = ((unsigned)(xi+1) < 64u) ? 1.f : 0.f;
    float vy0 = ((unsigned)yi     < 64u) ? 1.f : 0.f;
    float vy1 = ((unsigned)(yi+1) < 64u) ? 1.f : 0.f;
    int cx0 = min(max(xi,0),63),   cx1 = min(max(xi+1,0),63);
    int cy0 = min(max(yi,0),63),   cy1 = min(max(yi+1,0),63);
    float w00 = (1.f-ax)*(1.f-ay)*vx0*vy0;
    float w01 = ax*(1.f-ay)*vx1*vy0;
    float w10 = (1.f-ax)*ay*vx0*vy1;
    float w11 = ax*ay*vx1*vy1;
    const float* f1b = f1c + (size_t)b*262144;
    const float* f0b = f0c + (size_t)b*262144;
    int i00 = cy0*64+cx0, i01 = cy0*64+cx1, i10 = cy1*64+cx0, i11 = cy1*64+cx1;
    int cs = blockIdx.y*16;
    for (int c=cs;c<cs+16;c++) {
        const float* fc = f1b + (size_t)c*4096;
        float v = w00*fc[i00] + w01*fc[i01] + w10*fc[i10] + w11*fc[i11];
        xb[(size_t)(64+c)*4096 + p] = v;
        xb[(size_t)c*4096 + p]      = f0b[(size_t)c*4096 + p];
    }
}

// ---------------- tf32 tensor-core 3x3 conv, SAME pad, no bias ----------------
// Block: 32 oc x (16 rows x 32 cols). 8 warps; warp w owns output rows 2w, 2w+1.
// Per warp per row: 2 M-tiles (16 px) x 4 N-tiles (8 oc) of mma.m16n8k8 (K=8 ic),
// 3xTF32 precision split, fp32 accumulators. B fragments split once per (kh,kw),
// reused for both rows. smem ic pad 9 -> frag LDS banks 9g+t, conflict-free.
// Double-buffered cp.async.
template<int CINP>
__global__ void __launch_bounds__(256,2) conv3x3_mma(
    const float* __restrict__ in, const float* __restrict__ wgt,
    float* __restrict__ out, int cinReal, int cout, int H, int W)
{
    __shared__ __align__(16) float sIn[2][18][34][9];
    __shared__ __align__(16) float sW[2][9][32][9];
    const int HW = H*W;
    const int tilesX = W >> 5;
    const int tx = blockIdx.x % tilesX;
    const int ty = blockIdx.x / tilesX;
    const int ocb = blockIdx.y << 5;
    const int b = blockIdx.z;
    const int tid = threadIdx.x;
    const int lane = tid & 31;
    const int wid = tid >> 5;      // warp -> output rows 2w, 2w+1
    const int g = lane >> 2;       // group 0..7
    const int t = lane & 3;        // thread-in-group 0..3
    const int x0 = tx << 5, y0 = ty << 4;
    const float* inB = in + (size_t)b*CINP*HW;
    constexpr int NCH = CINP/8;

    auto stage = [&](int buf, int c0) {
        for (int idx=tid; idx<4896; idx+=256) {       // 18 x 34 x 8ic
            int ic = idx/612;
            int rem = idx - ic*612;
            int r  = rem/34;
            int cl = rem - r*34;
            int yy = y0-1+r, xx = x0-1+cl;
            bool ok = ((unsigned)yy < (unsigned)H) && ((unsigned)xx < (unsigned)W);
            int yc = min(max(yy,0),H-1), xc = min(max(xx,0),W-1);
            const float* src = inB + (size_t)(c0+ic)*HW + yc*W + xc;
            cp_async4(smem_u32(&sIn[buf][r][cl][ic]), src, ok ? 4 : 0);
        }
        for (int idx=tid; idx<2304; idx+=256) {       // 9k x 32oc x 8ic
            int ic = idx/288;
            int rem = idx - ic*288;
            int k  = rem >> 5;
            int o  = rem & 31;
            int icg = c0 + ic;
            int icc = min(icg, cinReal-1);
            const float* src = wgt + ((size_t)(ocb+o)*cinReal + icc)*9 + k;
            cp_async4(smem_u32(&sW[buf][k][o][ic]), src, (icg < cinReal) ? 4 : 0);
        }
        cp_commit();
    };

    float c[2][2][4][4];
#pragma unroll
    for (int rr=0;rr<2;rr++)
#pragma unroll
        for (int m=0;m<2;m++)
#pragma unroll
            for (int n=0;n<4;n++)
#pragma unroll
                for (int e=0;e<4;e++) c[rr][m][n][e] = 0.f;

    stage(0, 0);

    for (int ci=0; ci<NCH; ci++) {
        if (ci+1 < NCH) {
            stage((ci+1)&1, (ci+1)*8);
            cp_wait1();
        } else {
            cp_wait0();
        }
        __syncthreads();
        const int buf = ci & 1;
#pragma unroll
        for (int kh=0;kh<3;kh++) {
#pragma unroll
            for (int kw=0;kw<3;kw++) {
                // B fragments: split once, reuse for both rows
                const float* wp = &sW[buf][kh*3+kw][0][0]; // [32][9]
                uint32_t Bhi[4][2], Blo[4][2];
#pragma unroll
                for (int n=0;n<4;n++) {
                    float h0 = wp[(8*n+g)*9 + t];
                    float h1 = wp[(8*n+g)*9 + t + 4];
                    tf32split(h0, Bhi[n][0], Blo[n][0]);
                    tf32split(h1, Bhi[n][1], Blo[n][1]);
                }
#pragma unroll
                for (int rr=0;rr<2;rr++) {
                    const float* rowp = &sIn[buf][2*wid+rr+kh][0][0];  // [34][9]
                    uint32_t Ahi[2][4], Alo[2][4];
#pragma unroll
                    for (int m=0;m<2;m++) {
                        int xb = 16*m + kw + g;
                        float f0 = rowp[xb*9 + t];
                        float f1 = rowp[(xb+8)*9 + t];
                        float f2 = rowp[xb*9 + t + 4];
                        float f3 = rowp[(xb+8)*9 + t + 4];
                        tf32split(f0, Ahi[m][0], Alo[m][0]);
                        tf32split(f1, Ahi[m][1], Alo[m][1]);
                        tf32split(f2, Ahi[m][2], Alo[m][2]);
                        tf32split(f3, Ahi[m][3], Alo[m][3]);
                    }
#pragma unroll
                    for (int m=0;m<2;m++)
#pragma unroll
                        for (int n=0;n<4;n++) {
                            mma_tf32(c[rr][m][n], Ahi[m], Bhi[n]);
                            mma_tf32(c[rr][m][n], Ahi[m], Blo[n]);
                            mma_tf32(c[rr][m][n], Alo[m], Bhi[n]);
                        }
                }
            }
        }
        __syncthreads();
    }

#pragma unroll
    for (int rr=0;rr<2;rr++) {
        const int oy = y0 + 2*wid + rr;
#pragma unroll
        for (int m=0;m<2;m++) {
#pragma unroll
            for (int n=0;n<4;n++) {
                int oc = ocb + 8*n + 2*t;
                float* p0 = out + ((size_t)b*cout + oc)*HW + oy*W + x0 + 16*m + g;
                p0[0] = c[rr][m][n][0];
                p0[8] = c[rr][m][n][2];
                float* p1 = p0 + HW;
                p1[0] = c[rr][m][n][1];
                p1[8] = c[rr][m][n][3];
            }
        }
    }
}

// ---------------- batch-norm: per-channel stats over (B,H,W) ----------------
__global__ void bn_reduce(const float* __restrict__ x, int C, int HW)
{
    const int c = blockIdx.x;
    const int tid = threadIdx.x;
    const int HW4 = HW >> 2;
    float s = 0.f, s2 = 0.f;
    for (int b=0;b<4;b++) {
        const float4* xb = (const float4*)(x + ((size_t)b*C + c)*HW);
        for (int p=tid; p<HW4; p+=256) {
            float4 v = xb[p];
            s  += v.x + v.y + v.z + v.w;
            s2 += v.x*v.x + v.y*v.y + v.z*v.z + v.w*v.w;
        }
    }
    __shared__ float rs[256];
    __shared__ float rq[256];
    rs[tid] = s; rq[tid] = s2;
    __syncthreads();
    for (int off=128; off>0; off>>=1) {
        if (tid < off) { rs[tid]+=rs[tid+off]; rq[tid]+=rq[tid+off]; }
        __syncthreads();
    }
    if (tid == 0) {
        float invN = 1.0f/(4.0f*HW);
        float m = rs[0]*invN;
        float var = rq[0]*invN - m*m;
        g_mean[c] = m;
        g_istd[c] = rsqrtf(var + 1e-5f);
    }
}

// in-place BN + ReLU, float4 vectorized (HW multiple of 4)
__global__ void bn_apply(float* __restrict__ x, int cMask, int hwShift)
{
    int idx = blockIdx.x*256 + threadIdx.x;   // element/4 index
    int c = (idx >> (hwShift-2)) & cMask;
    float m = g_mean[c], is = g_istd[c];
    float4 v = ((float4*)x)[idx];
    v.x = fmaxf((v.x - m)*is, 0.f);
    v.y = fmaxf((v.y - m)*is, 0.f);
    v.z = fmaxf((v.z - m)*is, 0.f);
    v.w = fmaxf((v.w - m)*is, 0.f);
    ((float4*)x)[idx] = v;
}

// ---------------- heads (1x1 conv + bias + residual) ----------------
__global__ void head_coarse(const float* __restrict__ w, const float* __restrict__ bias,
                            float* __restrict__ out)
{
    __shared__ float sw[768];
    for (int idx=threadIdx.x; idx<768; idx+=256) sw[idx] = w[idx];
    __syncthreads();
    int i = blockIdx.x*256 + threadIdx.x;     // 16384
    int b = i>>12, p = i&4095;
    const float* xb = g_bufB + (size_t)b*256*4096 + p;
    float a0 = bias[0], a1 = bias[1], a2 = bias[2];
    for (int c=0;c<256;c++) {
        float v = xb[(size_t)c*4096];
        a0 = fmaf(v, sw[c],     a0);
        a1 = fmaf(v, sw[256+c], a1);
        a2 = fmaf(v, sw[512+c], a2);
    }
    out[(size_t)(b*3  )*4096 + p] = g_warp[(size_t)(b*2  )*4096 + p] + a0;
    out[(size_t)(b*3+1)*4096 + p] = g_warp[(size_t)(b*2+1)*4096 + p] + a1;
    out[(size_t)(b*3+2)*4096 + p] = a2;
}

// ---------------- 2x bilinear upsample (half-pixel, edge-clamped) ----------------
__global__ void upsample_kernel(const float* __restrict__ cm)
{
    int idx = blockIdx.x*256 + threadIdx.x;   // 196608
    if (idx >= 196608) return;
    int p  = idx & 16383;
    int bc = idx >> 14;
    int ox = p & 127, oy = p >> 7;
    float sx = 0.5f*ox - 0.25f;
    float sy = 0.5f*oy - 0.25f;
    float fx = floorf(sx), fy = floorf(sy);
    float ax = sx - fx, ay = sy - fy;
    int x0 = (int)fx, y0 = (int)fy;
    int x0c = max(x0,0), x1c = min(x0+1,63);
    int y0c = max(y0,0), y1c = min(y0+1,63);
    const float* inb = cm + (size_t)bc*4096;
    float v00 = inb[y0c*64+x0c], v01 = inb[y0c*64+x1c];
    float v10 = inb[y1c*64+x0c], v11 = inb[y1c*64+x1c];
    g_up[idx] = (1.f-ay)*((1.f-ax)*v00 + ax*v01) + ay*((1.f-ax)*v10 + ax*v11);
}

// ---------------- fine concat + grid_sample ----------------
__global__ void pack_fine(const float* __restrict__ f0f, const float* __restrict__ f1f)
{
    int i = blockIdx.x*256 + threadIdx.x;     // 65536
    if (i >= 65536) return;
    int b = i>>14, p = i&16383;
    float wx = g_up[(size_t)(b*3  )*16384 + p];
    float wy = g_up[(size_t)(b*3+1)*16384 + p];
    float* yb = g_cat + (size_t)b*56*16384;
    if (blockIdx.y == 0) {
        yb[(size_t)48*16384 + p] = wx;
        yb[(size_t)49*16384 + p] = wy;
#pragma unroll
        for (int c=50;c<56;c++) yb[(size_t)c*16384 + p] = 0.f;
    }

    float fx = (wx + 1.f)*64.f - 0.5f;
    float fy = (wy + 1.f)*64.f - 0.5f;
    float flx = floorf(fx), fly = floorf(fy);
    float ax = fx - flx, ay = fy - fly;
    int xi = (int)flx, yi = (int)fly;
    float vx0 = ((unsigned)xi     < 128u) ? 1.f : 0.f;
    float vx1 = ((unsigned)(xi+1) < 128u) ? 1.f : 0.f;
    float vy0 = ((unsigned)yi     < 128u) ? 1.f : 0.f;
    float vy1 = ((unsigned)(yi+1) < 128u) ? 1.f : 0.f;
    int cx0 = min(max(xi,0),127),  cx1 = min(max(xi+1,0),127);
    int cy0 = min(max(yi,0),127),  cy1 = min(max(yi+1,0),127);
    float w00 = (1.f-ax)*(1.f-ay)*vx0*vy0;
    float w01 = ax*(1.f-ay)*vx1*vy0;
    float w10 = (1.f-ax)*ay*vx0*vy1;
    float w11 = ax*ay*vx1*vy1;
    const float* f1b = f1f + (size_t)b*24*16384;
    const float* f0b = f0f + (size_t)b*24*16384;
    int i00 = cy0*128+cx0, i01 = cy0*128+cx1, i10 = cy1*128+cx0, i11 = cy1*128+cx1;
    int cs = blockIdx.y*6;
    for (int c=cs;c<cs+6;c++) {
        const float* fc = f1b + (size_t)c*16384;
        float v = w00*fc[i00] + w01*fc[i01] + w10*fc[i10] + w11*fc[i11];
        yb[(size_t)(24+c)*16384 + p] = v;
        yb[(size_t)c*16384 + p]      = f0b[(size_t)c*16384 + p];
    }
}

__global__ void head_fine(const float* __restrict__ w, const float* __restrict__ bias,
                          float* __restrict__ out)
{
    __shared__ float sw[192];
    for (int idx=threadIdx.x; idx<192; idx+=256) sw[idx] = w[idx];
    __syncthreads();
    int i = blockIdx.x*256 + threadIdx.x;     // 65536
    int b = i>>14, p = i&16383;
    const float* yb = g_bufB + (size_t)b*64*16384 + p;
    float a0 = bias[0], a1 = bias[1], a2 = bias[2];
    for (int c=0;c<64;c++) {
        float v = yb[(size_t)c*16384];
        a0 = fmaf(v, sw[c],      a0);
        a1 = fmaf(v, sw[64+c],   a1);
        a2 = fmaf(v, sw[128+c],  a2);
    }
    out[(size_t)(b*3  )*16384 + p] = g_up[(size_t)(b*3  )*16384 + p] + a0;
    out[(size_t)(b*3+1)*16384 + p] = g_up[(size_t)(b*3+1)*16384 + p] + a1;
    out[(size_t)(b*3+2)*16384 + p] = g_up[(size_t)(b*3+2)*16384 + p] + a2;
}

// ---------------- launch ----------------
extern "C" void kernel_launch(void* const* d_in, const int* in_sizes, int n_in,
                              void* d_out, int out_size)
{
    const float* f0c = (const float*)d_in[0];
    const float* f1c = (const float*)d_in[1];
    const float* f0f = (const float*)d_in[2];
    const float* f1f = (const float*)d_in[3];
    const float* cw1 = (const float*)d_in[4];
    const float* cw2 = (const float*)d_in[5];
    const float* cw3 = (const float*)d_in[6];
    const float* cw4 = (const float*)d_in[7];
    const float* cw5 = (const float*)d_in[8];
    const float* cb5 = (const float*)d_in[9];
    const float* fw1 = (const float*)d_in[10];
    const float* fw2 = (const float*)d_in[11];
    const float* fw3 = (const float*)d_in[12];
    const float* fw4 = (const float*)d_in[13];
    const float* fw5 = (const float*)d_in[14];
    const float* fb5 = (const float*)d_in[15];

    float *pCat, *pA, *pB;
    cudaGetSymbolAddress((void**)&pCat, g_cat);
    cudaGetSymbolAddress((void**)&pA,   g_bufA);
    cudaGetSymbolAddress((void**)&pB,   g_bufB);

    float* outC = (float*)d_out;          // (4,3,64,64)
    float* outF = outC + 49152;           // (4,3,128,128)

    // coarse attention -> warp field
    attn_kernel<<<dim3(16,4,4),256>>>(f0c, f1c);
    attn_combine<<<64,256>>>();
    pack_coarse<<<dim3(64,4),256>>>(f0c, f1c);

    // coarse conv tower: conv -> stats -> in-place BN+ReLU
    // conv grid: (tilesX*tilesY, cout/32, B) = (2*4, 8, 4) = 256 blocks
    conv3x3_mma<136><<<dim3(8,8,4),256>>>(pCat, cw1, pA, 130, 256, 64, 64);
    bn_reduce<<<256,256>>>(pA, 256, 4096);
    bn_apply<<<4096,256>>>(pA, 255, 12);
    conv3x3_mma<256><<<dim3(8,8,4),256>>>(pA, cw2, pB, 256, 256, 64, 64);
    bn_reduce<<<256,256>>>(pB, 256, 4096);
    bn_apply<<<4096,256>>>(pB, 255, 12);
    conv3x3_mma<256><<<dim3(8,8,4),256>>>(pB, cw3, pA, 256, 256, 64, 64);
    bn_reduce<<<256,256>>>(pA, 256, 4096);
    bn_apply<<<4096,256>>>(pA, 255, 12);
    conv3x3_mma<256><<<dim3(8,8,4),256>>>(pA, cw4, pB, 256, 256, 64, 64);
    bn_reduce<<<256,256>>>(pB, 256, 4096);
    bn_apply<<<4096,256>>>(pB, 255, 12);

    head_coarse<<<64,256>>>(cw5, cb5, outC);

    // fine stage
    upsample_kernel<<<768,256>>>(outC);
    pack_fine<<<dim3(256,4),256>>>(f0f, f1f);

    // fine conv grid: (4*8, 2, 4) = 256 blocks
    conv3x3_mma<56><<<dim3(32,2,4),256>>>(pCat, fw1, pA, 50, 64, 128, 128);
    bn_reduce<<<64,256>>>(pA, 64, 16384);
    bn_apply<<<4096,256>>>(pA, 63, 14);
    conv3x3_mma<64><<<dim3(32,2,4),256>>>(pA, fw2, pB, 64, 64, 128, 128);
    bn_reduce<<<64,256>>>(pB, 64, 16384);
    bn_apply<<<4096,256>>>(pB, 63, 14);
    conv3x3_mma<64><<<dim3(32,2,4),256>>>(pB, fw3, pA, 64, 64, 128, 128);
    bn_reduce<<<64,256>>>(pA, 64, 16384);
    bn_apply<<<4096,256>>>(pA, 63, 14);
    conv3x3_mma<64><<<dim3(32,2,4),256>>>(pA, fw4, pB, 64, 64, 128, 128);
    bn_reduce<<<64,256>>>(pB, 64, 16384);
    bn_apply<<<4096,256>>>(pB, 63, 14);

    head_fine<<<256,256>>>(fw5, fb5, outF);
}